// round 4
// baseline (speedup 1.0000x reference)
#include <cuda_runtime.h>
#include <math.h>

#define Bn 8
#define Cc 128
#define Nn 4096
#define Kk 16
#define Hh 64
#define Pp (Bn*Nn)          // 32768 points total
#define FLT_BIG 3.402823466e+38f

// ---------------- static device scratch (no allocations allowed) ----------------
__device__ float g_qT[Pp*Cc];        // q transposed  [P][C]
__device__ float g_kT[Pp*Cc];        // k transposed  [P][C]
__device__ float g_vT[Pp*Cc];        // v transposed  [P][C]
__device__ float g_fT[Pp*Cc];        // feats transposed [P][C]
__device__ float g_agg[Pp*Cc];       // aggregated features [P][C]
__device__ float g_hid[Pp*2*Cc];     // out-MLP hidden [P][2C]
__device__ float g_t[Pp*Hh*Kk];      // BN pre-activation [P][H][K]  (134MB)
__device__ int   g_idx[Pp*Kk];       // knn indices (GLOBAL point ids)
__device__ float g_sq[Pp];           // |pts|^2
__device__ double g_bnsum[Hh];
__device__ double g_bnss[Hh];
__device__ float g_bnscale[Hh];
__device__ float g_bnshift[Hh];

// ---------------- kernel 0: squared norms + zero BN accumulators ----------------
__global__ void k_sq(const float* __restrict__ pts) {
    int p = blockIdx.x * 256 + threadIdx.x;
    if (p < Hh) { g_bnsum[p] = 0.0; g_bnss[p] = 0.0; }
    if (p >= Pp) return;
    int b = p >> 12, n = p & (Nn - 1);
    const float* pb = pts + b * 3 * Nn;
    float x = pb[n], y = pb[Nn + n], z = pb[2 * Nn + n];
    g_sq[p] = x * x + y * y + z * z;
}

// ---------------- kernel 1: kNN (one warp per query point) ----------------
__global__ __launch_bounds__(256) void k_knn(const float* __restrict__ pts) {
    __shared__ float sd[8][32][16];
    __shared__ int   si[8][32][16];
    int w = threadIdx.x >> 5, lane = threadIdx.x & 31;
    int p = blockIdx.x * 8 + w;
    int b = p >> 12, n = p & (Nn - 1);
    const float* pb = pts + b * 3 * Nn;
    float qx = pb[n], qy = pb[Nn + n], qz = pb[2 * Nn + n];
    float sqn = g_sq[p];
    const float* sqb = g_sq + b * Nn;

    float* buf = sd[w][lane];
    int*   ib  = si[w][lane];
#pragma unroll
    for (int t = 0; t < 16; t++) buf[t] = FLT_BIG;
    float maxv = FLT_BIG; int maxslot = 0;

    for (int m = lane; m < Nn; m += 32) {
        float px = pb[m], py = pb[Nn + m], pz = pb[2 * Nn + m];
        float inner = fmaf(qx, px, fmaf(qy, py, qz * pz));
        float d = sqn + sqb[m] - 2.0f * inner;
        if (d < maxv) {
            buf[maxslot] = d; ib[maxslot] = m;
            maxv = buf[0]; maxslot = 0;
#pragma unroll
            for (int t = 1; t < 16; t++)
                if (buf[t] > maxv) { maxv = buf[t]; maxslot = t; }
        }
    }
    __syncwarp();
    // 16 rounds of global min extraction across the 32 lanes
    for (int t = 0; t < 16; t++) {
        float mv = buf[0]; int ms = 0;
#pragma unroll
        for (int s = 1; s < 16; s++)
            if (buf[s] < mv) { mv = buf[s]; ms = s; }
        float v = mv; int id = ib[ms]; int src = lane;
#pragma unroll
        for (int off = 16; off; off >>= 1) {
            float vo = __shfl_xor_sync(0xffffffffu, v, off);
            int io = __shfl_xor_sync(0xffffffffu, id, off);
            int so = __shfl_xor_sync(0xffffffffu, src, off);
            if (vo < v || (vo == v && so < src)) { v = vo; id = io; src = so; }
        }
        if (lane == src) buf[ms] = FLT_BIG;
        if (lane == 0) g_idx[p * Kk + t] = id + (b << 12);   // GLOBAL index
        __syncwarp();
    }
}

// ---------------- kernel 2: q/k/v GEMMs with transposed output ----------------
__global__ __launch_bounds__(256) void k_qkv(const float* __restrict__ feats,
    const float* __restrict__ Wq, const float* __restrict__ bq,
    const float* __restrict__ Wk, const float* __restrict__ bk,
    const float* __restrict__ Wv, const float* __restrict__ bv) {
    const float* W; const float* bias; float* out;
    if (blockIdx.z == 0)      { W = Wq; bias = bq; out = g_qT; }
    else if (blockIdx.z == 1) { W = Wk; bias = bk; out = g_kT; }
    else                      { W = Wv; bias = bv; out = g_vT; }
    __shared__ float As[64 * 33], Ws[64 * 33];
    int tid = threadIdx.x;
    int p0 = blockIdx.x * 64;
    int b = p0 >> 12; int n0 = p0 & (Nn - 1);
    const float* fb = feats + b * Cc * Nn;
    int o0 = blockIdx.y * 64;
    int tx = tid & 15, ty = tid >> 4;
    float acc[4][4] = {};
    for (int k0 = 0; k0 < Cc; k0 += 32) {
        int e = tid * 8;
        int ppb = e & 63, kk = e >> 6;
        const float* src = fb + (k0 + kk) * Nn + n0 + ppb;
#pragma unroll
        for (int u = 0; u < 8; u++) As[(ppb + u) * 33 + kk] = src[u];
        int oo = tid >> 2, kb = (tid & 3) * 8;
        const float* wsrc = W + (o0 + oo) * Cc + k0 + kb;
#pragma unroll
        for (int u = 0; u < 8; u++) Ws[oo * 33 + kb + u] = wsrc[u];
        __syncthreads();
#pragma unroll 8
        for (int kq = 0; kq < 32; kq++) {
            float a[4], bb[4];
#pragma unroll
            for (int i = 0; i < 4; i++) a[i] = As[(ty + 16 * i) * 33 + kq];
#pragma unroll
            for (int j = 0; j < 4; j++) bb[j] = Ws[(tx + 16 * j) * 33 + kq];
#pragma unroll
            for (int i = 0; i < 4; i++)
#pragma unroll
                for (int j = 0; j < 4; j++) acc[i][j] = fmaf(a[i], bb[j], acc[i][j]);
        }
        __syncthreads();
    }
#pragma unroll
    for (int i = 0; i < 4; i++) {
        int p = p0 + ty + 16 * i;
#pragma unroll
        for (int j = 0; j < 4; j++) {
            int o = o0 + tx + 16 * j;
            out[p * Cc + o] = acc[i][j] + bias[o];
        }
    }
}

// ---------------- kernel 2b: feats transpose ----------------
__global__ void k_tr(const float* __restrict__ feats) {
    __shared__ float tile[32][33];
    int b = blockIdx.z;
    int n0 = blockIdx.x * 32, c0 = blockIdx.y * 32;
    int tx = threadIdx.x, ty = threadIdx.y;
#pragma unroll
    for (int r = 0; r < 32; r += 8)
        tile[ty + r][tx] = feats[b * Cc * Nn + (c0 + ty + r) * Nn + n0 + tx];
    __syncthreads();
#pragma unroll
    for (int r = 0; r < 32; r += 8)
        g_fT[((long)b * Nn + n0 + ty + r) * Cc + c0 + tx] = tile[tx][ty + r];
}

// ---------------- kernel 3: pass1 (geo MLP + rel conv -> t, BN stats) ----------------
// 8 points per block, J = 128 = 8*16 (point,neighbor) columns
__global__ __launch_bounds__(256) void k_pass1(const float* __restrict__ pts,
    const float* __restrict__ geo_W1, const float* __restrict__ geo_b1,
    const float* __restrict__ geo_W2, const float* __restrict__ geo_b2,
    const float* __restrict__ rel_W1, const float* __restrict__ rel_b1) {
    extern __shared__ float sm[];
    float* s_w   = sm;                  // 8192 (geo_W2 then rel_W1)
    float* s_g1  = s_w + 8192;          // [64][128]
    float* s_e   = s_g1 + 8192;         // [128][129]
    float* s_geo = s_e + 128 * 129;     // [3][128]
    float* s_sum = s_geo + 384;         // [64]
    float* s_ss  = s_sum + 64;          // [64]
    int*   s_idx = (int*)(s_ss + 64);   // [128]
    int tid = threadIdx.x;
    int p0 = blockIdx.x * 8;
    int b = p0 >> 12; int n0 = p0 & (Nn - 1);

    if (tid < 128) s_idx[tid] = g_idx[p0 * Kk + tid];
    for (int i = tid; i < 8192; i += 256) s_w[i] = geo_W2[i];
    __syncthreads();
    if (tid < 128) {
        int nb = s_idx[tid] & (Nn - 1);   // within-batch for pts
        int pl = tid >> 4;
        const float* pb = pts + b * 3 * Nn;
#pragma unroll
        for (int c = 0; c < 3; c++)
            s_geo[c * 128 + tid] = pb[c * Nn + n0 + pl] - pb[c * Nn + nb];
    }
    __syncthreads();
    // g1 = relu(geo_W1 @ rel_geo + b1)
    for (int idx = tid; idx < 8192; idx += 256) {
        int h = idx >> 7, j = idx & 127;
        float v = fmaf(geo_W1[h * 3 + 2], s_geo[256 + j],
                  fmaf(geo_W1[h * 3 + 1], s_geo[128 + j],
                  fmaf(geo_W1[h * 3 + 0], s_geo[j], geo_b1[h])));
        s_g1[idx] = fmaxf(v, 0.f);
    }
    __syncthreads();
    int tx = tid & 15, ty = tid >> 4;
    // geo_emb = geo_W2 @ g1 + b2   (128x128, k=64)
    {
        float acc[8][8] = {};
        for (int kk = 0; kk < 64; kk++) {
            float a[8], bb[8];
#pragma unroll
            for (int i = 0; i < 8; i++) a[i] = s_w[(ty + 16 * i) * 64 + kk];
#pragma unroll
            for (int j = 0; j < 8; j++) bb[j] = s_g1[kk * 128 + tx + 16 * j];
#pragma unroll
            for (int i = 0; i < 8; i++)
#pragma unroll
                for (int j = 0; j < 8; j++) acc[i][j] = fmaf(a[i], bb[j], acc[i][j]);
        }
#pragma unroll
        for (int i = 0; i < 8; i++) {
            int c = ty + 16 * i;
            float bc = geo_b2[c];
#pragma unroll
            for (int j = 0; j < 8; j++) s_e[c * 129 + tx + 16 * j] = acc[i][j] + bc;
        }
    }
    __syncthreads();
    // rel = q - knn_k + geo_emb (in place)
    {
        int c = tid & 127, jh = tid >> 7;
        for (int jo = 0; jo < 64; jo++) {
            int j = jo * 2 + jh;
            int pl = j >> 4;
            int nb = s_idx[j];                // GLOBAL index into g_kT
            s_e[c * 129 + j] += g_qT[(p0 + pl) * Cc + c] - g_kT[nb * Cc + c];
        }
    }
    __syncthreads();
    for (int i = tid; i < 8192; i += 256) s_w[i] = rel_W1[i];
    __syncthreads();
    // t = rel_W1 @ rel + b1  (64x128, k=128), write + BN partials
    {
        float acc[4][8] = {};
        for (int cc = 0; cc < 128; cc++) {
            float a[4], bb[8];
#pragma unroll
            for (int i = 0; i < 4; i++) a[i] = s_w[(ty + 16 * i) * 128 + cc];
#pragma unroll
            for (int j = 0; j < 8; j++) bb[j] = s_e[cc * 129 + tx + 16 * j];
#pragma unroll
            for (int i = 0; i < 4; i++)
#pragma unroll
                for (int j = 0; j < 8; j++) acc[i][j] = fmaf(a[i], bb[j], acc[i][j]);
        }
#pragma unroll
        for (int i = 0; i < 4; i++) {
            int h = ty + 16 * i;
            float bh = rel_b1[h];
            float rs = 0.f, rss = 0.f;
#pragma unroll
            for (int j = 0; j < 8; j++) {
                float v = acc[i][j] + bh;     // column j*16+tx -> point p0+j, k=tx
                g_t[(long)(p0 + j) * (Hh * Kk) + h * Kk + tx] = v;
                rs += v; rss += v * v;
            }
#pragma unroll
            for (int off = 8; off; off >>= 1) {
                rs  += __shfl_xor_sync(0xffffffffu, rs, off);
                rss += __shfl_xor_sync(0xffffffffu, rss, off);
            }
            if (tx == 0) { s_sum[h] = rs; s_ss[h] = rss; }
        }
    }
    __syncthreads();
    if (tid < 64) {
        atomicAdd(&g_bnsum[tid], (double)s_sum[tid]);
        atomicAdd(&g_bnss[tid],  (double)s_ss[tid]);
    }
}

// ---------------- kernel 4: BN finalize ----------------
__global__ void k_bnfin(const float* __restrict__ rel_g, const float* __restrict__ rel_beta) {
    int h = threadIdx.x;
    if (h >= Hh) return;
    double cnt = (double)Pp * Kk;
    double m = g_bnsum[h] / cnt;
    double var = g_bnss[h] / cnt - m * m;
    double inv = 1.0 / sqrt(var + 1e-5);
    double sc = (double)rel_g[h] * inv;
    g_bnscale[h] = (float)sc;
    g_bnshift[h] = (float)((double)rel_beta[h] - m * sc);
}

// ---------------- kernel 5: pass2 (attn + aggregation) ----------------
// 4 points per block, J = 64
__global__ __launch_bounds__(256) void k_pass2(const float* __restrict__ pts,
    const float* __restrict__ geo_W1, const float* __restrict__ geo_b1,
    const float* __restrict__ geo_W2, const float* __restrict__ geo_b2,
    const float* __restrict__ rel_W2, const float* __restrict__ rel_b2) {
    extern __shared__ float sm[];
    float* s_w   = sm;                 // 8192
    float* s_g1  = s_w + 8192;         // [64][65] (g1 then h2)
    float* s_e   = s_g1 + 4160;        // [128][65] geo_emb
    float* s_l   = s_e + 8320;         // [128][65] logits/attn
    float* s_geo = s_l + 8320;         // [3][64]
    int*   s_idx = (int*)(s_geo + 192);// [64]
    int tid = threadIdx.x;
    int p0 = blockIdx.x * 4;
    int b = p0 >> 12; int n0 = p0 & (Nn - 1);

    if (tid < 64) s_idx[tid] = g_idx[p0 * Kk + tid];
    for (int i = tid; i < 8192; i += 256) s_w[i] = geo_W2[i];
    __syncthreads();
    if (tid < 64) {
        int nb = s_idx[tid] & (Nn - 1);   // within-batch for pts
        int pl = tid >> 4;
        const float* pb = pts + b * 3 * Nn;
#pragma unroll
        for (int c = 0; c < 3; c++)
            s_geo[c * 64 + tid] = pb[c * Nn + n0 + pl] - pb[c * Nn + nb];
    }
    __syncthreads();
    for (int idx = tid; idx < 4096; idx += 256) {
        int h = idx >> 6, j = idx & 63;
        float v = fmaf(geo_W1[h * 3 + 2], s_geo[128 + j],
                  fmaf(geo_W1[h * 3 + 1], s_geo[64 + j],
                  fmaf(geo_W1[h * 3 + 0], s_geo[j], geo_b1[h])));
        s_g1[h * 65 + j] = fmaxf(v, 0.f);
    }
    __syncthreads();
    int tx = tid & 15, ty = tid >> 4;
    // geo_emb (128x64, k=64)
    {
        float acc[8][4] = {};
        for (int kk = 0; kk < 64; kk++) {
            float a[8], bb[4];
#pragma unroll
            for (int i = 0; i < 8; i++) a[i] = s_w[(ty + 16 * i) * 64 + kk];
#pragma unroll
            for (int j = 0; j < 4; j++) bb[j] = s_g1[kk * 65 + tx + 16 * j];
#pragma unroll
            for (int i = 0; i < 8; i++)
#pragma unroll
                for (int j = 0; j < 4; j++) acc[i][j] = fmaf(a[i], bb[j], acc[i][j]);
        }
#pragma unroll
        for (int i = 0; i < 8; i++) {
            int c = ty + 16 * i;
            float bc = geo_b2[c];
#pragma unroll
            for (int j = 0; j < 4; j++) s_e[c * 65 + tx + 16 * j] = acc[i][j] + bc;
        }
    }
    __syncthreads();
    // h2 = relu(BN(t)) into s_g1
    for (int idx = tid; idx < 4096; idx += 256) {
        int h = idx >> 6, j = idx & 63;
        float tv = g_t[(long)(p0 + (j >> 4)) * (Hh * Kk) + h * Kk + (j & 15)];
        float v = fmaf(g_bnscale[h], tv, g_bnshift[h]);
        s_g1[h * 65 + j] = fmaxf(v, 0.f);
    }
    __syncthreads();
    for (int i = tid; i < 8192; i += 256) s_w[i] = rel_W2[i];
    __syncthreads();
    // logits (128x64, k=64)
    {
        float acc[8][4] = {};
        for (int kk = 0; kk < 64; kk++) {
            float a[8], bb[4];
#pragma unroll
            for (int i = 0; i < 8; i++) a[i] = s_w[(ty + 16 * i) * 64 + kk];
#pragma unroll
            for (int j = 0; j < 4; j++) bb[j] = s_g1[kk * 65 + tx + 16 * j];
#pragma unroll
            for (int i = 0; i < 8; i++)
#pragma unroll
                for (int j = 0; j < 4; j++) acc[i][j] = fmaf(a[i], bb[j], acc[i][j]);
        }
#pragma unroll
        for (int i = 0; i < 8; i++) {
            int c = ty + 16 * i;
            float bc = rel_b2[c];
#pragma unroll
            for (int j = 0; j < 4; j++) s_l[c * 65 + tx + 16 * j] = acc[i][j] + bc;
        }
    }
    __syncthreads();
    // softmax over K per (c, point)
    for (int r = tid; r < 512; r += 256) {
        int c = r & 127, pl = r >> 7;
        float* row = s_l + c * 65 + pl * 16;
        float mx = row[0];
#pragma unroll
        for (int k = 1; k < 16; k++) mx = fmaxf(mx, row[k]);
        float ev[16]; float sum = 0.f;
#pragma unroll
        for (int k = 0; k < 16; k++) { ev[k] = expf(row[k] - mx); sum += ev[k]; }
        float inv = 1.f / sum;
#pragma unroll
        for (int k = 0; k < 16; k++) row[k] = ev[k] * inv;
    }
    __syncthreads();
    // agg = sum_k attn * (v + geo_emb) + feats
    {
        int c = tid & 127, ph = tid >> 7;
#pragma unroll
        for (int plo = 0; plo < 2; plo++) {
            int pl = ph + 2 * plo;
            float acc = 0.f;
#pragma unroll
            for (int k = 0; k < 16; k++) {
                int j = pl * 16 + k;
                int nb = s_idx[j];            // GLOBAL index into g_vT
                acc = fmaf(s_l[c * 65 + j], g_vT[nb * Cc + c] + s_e[c * 65 + j], acc);
            }
            g_agg[(p0 + pl) * Cc + c] = acc + g_fT[(p0 + pl) * Cc + c];
        }
    }
}

// ---------------- kernel 6: out MLP layer 1 (relu) ----------------
__global__ __launch_bounds__(256) void k_mlp1(const float* __restrict__ W, const float* __restrict__ bias) {
    __shared__ float As[64 * 33], Ws[64 * 33];
    int tid = threadIdx.x;
    int p0 = blockIdx.x * 64, o0 = blockIdx.y * 64;
    int tx = tid & 15, ty = tid >> 4;
    float acc[4][4] = {};
    for (int k0 = 0; k0 < Cc; k0 += 32) {
        int pp = tid >> 2, kb = (tid & 3) * 8;
        const float* a = g_agg + (p0 + pp) * Cc + k0 + kb;
#pragma unroll
        for (int u = 0; u < 8; u++) As[pp * 33 + kb + u] = a[u];
        const float* w = W + (o0 + pp) * Cc + k0 + kb;
#pragma unroll
        for (int u = 0; u < 8; u++) Ws[pp * 33 + kb + u] = w[u];
        __syncthreads();
#pragma unroll 8
        for (int kk = 0; kk < 32; kk++) {
            float av[4], bv[4];
#pragma unroll
            for (int i = 0; i < 4; i++) av[i] = As[(ty + 16 * i) * 33 + kk];
#pragma unroll
            for (int j = 0; j < 4; j++) bv[j] = Ws[(tx + 16 * j) * 33 + kk];
#pragma unroll
            for (int i = 0; i < 4; i++)
#pragma unroll
                for (int j = 0; j < 4; j++) acc[i][j] = fmaf(av[i], bv[j], acc[i][j]);
        }
        __syncthreads();
    }
#pragma unroll
    for (int i = 0; i < 4; i++) {
        int p = p0 + ty + 16 * i;
#pragma unroll
        for (int j = 0; j < 4; j++) {
            int o = o0 + tx + 16 * j;
            g_hid[p * (2 * Cc) + o] = fmaxf(acc[i][j] + bias[o], 0.f);
        }
    }
}

// ---------------- kernel 7: out MLP layer 2 + residual, [B,C,N] output ----------------
__global__ __launch_bounds__(256) void k_mlp2(const float* __restrict__ W, const float* __restrict__ bias,
                                              float* __restrict__ out) {
    __shared__ float As[64 * 33], Ws[64 * 33];
    int tid = threadIdx.x;
    int p0 = blockIdx.x * 64, o0 = blockIdx.y * 64;
    int tx = tid & 15, ty = tid >> 4;
    float acc[4][4] = {};
    for (int k0 = 0; k0 < 2 * Cc; k0 += 32) {
        int pp = tid >> 2, kb = (tid & 3) * 8;
        const float* a = g_hid + (p0 + pp) * (2 * Cc) + k0 + kb;
#pragma unroll
        for (int u = 0; u < 8; u++) As[pp * 33 + kb + u] = a[u];
        const float* w = W + (o0 + pp) * (2 * Cc) + k0 + kb;
#pragma unroll
        for (int u = 0; u < 8; u++) Ws[pp * 33 + kb + u] = w[u];
        __syncthreads();
#pragma unroll 8
        for (int kk = 0; kk < 32; kk++) {
            float av[4], bv[4];
#pragma unroll
            for (int i = 0; i < 4; i++) av[i] = As[(tx + 16 * i) * 33 + kk];
#pragma unroll
            for (int j = 0; j < 4; j++) bv[j] = Ws[(ty + 16 * j) * 33 + kk];
#pragma unroll
            for (int i = 0; i < 4; i++)
#pragma unroll
                for (int j = 0; j < 4; j++) acc[i][j] = fmaf(av[i], bv[j], acc[i][j]);
        }
        __syncthreads();
    }
#pragma unroll
    for (int i = 0; i < 4; i++) {
        int p = p0 + tx + 16 * i;
        int b = p >> 12, n = p & (Nn - 1);
#pragma unroll
        for (int j = 0; j < 4; j++) {
            int o = o0 + ty + 16 * j;
            out[(long)b * Cc * Nn + o * Nn + n] = acc[i][j] + bias[o] + g_agg[p * Cc + o];
        }
    }
}

// ---------------- launch ----------------
#define SMEM_P1 (33536 * 4)
#define SMEM_P2 (29248 * 4)

extern "C" void kernel_launch(void* const* d_in, const int* in_sizes, int n_in,
                              void* d_out, int out_size) {
    const float* pts   = (const float*)d_in[0];
    const float* feats = (const float*)d_in[1];
    const float* Wq = (const float*)d_in[2];  const float* bq = (const float*)d_in[3];
    const float* Wk = (const float*)d_in[4];  const float* bk = (const float*)d_in[5];
    const float* Wv = (const float*)d_in[6];  const float* bv = (const float*)d_in[7];
    const float* gW1 = (const float*)d_in[8]; const float* gb1 = (const float*)d_in[9];
    const float* gW2 = (const float*)d_in[10];const float* gb2 = (const float*)d_in[11];
    const float* rW1 = (const float*)d_in[12];const float* rb1 = (const float*)d_in[13];
    const float* rg  = (const float*)d_in[14];const float* rbe = (const float*)d_in[15];
    const float* rW2 = (const float*)d_in[16];const float* rb2 = (const float*)d_in[17];
    const float* oW1 = (const float*)d_in[18];const float* ob1 = (const float*)d_in[19];
    const float* oW2 = (const float*)d_in[20];const float* ob2 = (const float*)d_in[21];
    float* out = (float*)d_out;

    cudaFuncSetAttribute(k_pass1, cudaFuncAttributeMaxDynamicSharedMemorySize, SMEM_P1);
    cudaFuncSetAttribute(k_pass2, cudaFuncAttributeMaxDynamicSharedMemorySize, SMEM_P2);

    k_sq  <<<Pp / 256, 256>>>(pts);
    k_qkv <<<dim3(Pp / 64, 2, 3), 256>>>(feats, Wq, bq, Wk, bk, Wv, bv);
    k_tr  <<<dim3(Nn / 32, Cc / 32, Bn), dim3(32, 8)>>>(feats);
    k_knn <<<Pp / 8, 256>>>(pts);
    k_pass1<<<Pp / 8, 256, SMEM_P1>>>(pts, gW1, gb1, gW2, gb2, rW1, rb1);
    k_bnfin<<<1, 64>>>(rg, rbe);
    k_pass2<<<Pp / 4, 256, SMEM_P2>>>(pts, gW1, gb1, gW2, gb2, rW2, rb2);
    k_mlp1<<<dim3(Pp / 64, 4), 256>>>(oW1, ob1);
    k_mlp2<<<dim3(Pp / 64, 2), 256>>>(oW2, ob2, out);
}

// round 5
// speedup vs baseline: 1.1933x; 1.1933x over previous
#include <cuda_runtime.h>
#include <math.h>

#define Bn 8
#define Cc 128
#define Nn 4096
#define Kk 16
#define Hh 64
#define Pp (Bn*Nn)          // 32768 points total
#define FLT_BIG 3.402823466e+38f

// ---------------- static device scratch (no allocations allowed) ----------------
__device__ float g_qT[Pp*Cc];        // q transposed  [P][C]
__device__ float g_kT[Pp*Cc];        // k transposed  [P][C]
__device__ float g_vT[Pp*Cc];        // v transposed  [P][C]
__device__ float g_fT[Pp*Cc];        // feats transposed [P][C]
__device__ float g_agg[Pp*Cc];       // aggregated features [P][C]
__device__ float g_hid[Pp*2*Cc];     // out-MLP hidden [P][2C]
__device__ float g_t[Pp*Hh*Kk];      // BN pre-activation [P][H][K]  (134MB)
__device__ int   g_idx[Pp*Kk];       // knn indices (GLOBAL point ids)
__device__ float g_sq[Pp];           // |pts|^2
__device__ double g_bnsum[Hh];
__device__ double g_bnss[Hh];
__device__ float g_bnscale[Hh];
__device__ float g_bnshift[Hh];

// ---------------- kernel 0: squared norms + zero BN accumulators ----------------
__global__ void k_sq(const float* __restrict__ pts) {
    int p = blockIdx.x * 256 + threadIdx.x;
    if (p < Hh) { g_bnsum[p] = 0.0; g_bnss[p] = 0.0; }
    if (p >= Pp) return;
    int b = p >> 12, n = p & (Nn - 1);
    const float* pb = pts + b * 3 * Nn;
    float x = pb[n], y = pb[Nn + n], z = pb[2 * Nn + n];
    g_sq[p] = x * x + y * y + z * z;
}

// ---------------- kernel 1: kNN (one warp per query, register top-16) ----------------
__global__ __launch_bounds__(256) void k_knn(const float* __restrict__ pts) {
    __shared__ float sd[8][32][17];
    __shared__ int   si[8][32][17];
    int w = threadIdx.x >> 5, lane = threadIdx.x & 31;
    int p = blockIdx.x * 8 + w;
    int b = p >> 12, n = p & (Nn - 1);
    const float* pb = pts + b * 3 * Nn;
    float qx = pb[n], qy = pb[Nn + n], qz = pb[2 * Nn + n];
    float sqn = g_sq[p];
    const float* sqb = g_sq + b * Nn;

    // register-resident sorted (ascending) top-16
    float bd[16]; int bi[16];
#pragma unroll
    for (int t = 0; t < 16; t++) { bd[t] = FLT_BIG; bi[t] = 0; }

    for (int m = lane; m < Nn; m += 32) {
        float px = pb[m], py = pb[Nn + m], pz = pb[2 * Nn + m];
        float inner = fmaf(qx, px, fmaf(qy, py, qz * pz));
        float d = sqn + sqb[m] - 2.0f * inner;
        if (d < bd[15]) {
            bd[15] = d; bi[15] = m;
#pragma unroll
            for (int t = 15; t > 0; t--) {
                if (bd[t] < bd[t - 1]) {
                    float tv = bd[t]; bd[t] = bd[t - 1]; bd[t - 1] = tv;
                    int   ti = bi[t]; bi[t] = bi[t - 1]; bi[t - 1] = ti;
                }
            }
        }
    }
    // dump sorted buffers to SMEM
#pragma unroll
    for (int t = 0; t < 16; t++) { sd[w][lane][t] = bd[t]; si[w][lane][t] = bi[t]; }
    __syncwarp();

    // 16 merge rounds: per-lane head pointer (buffers sorted), warp argmin
    int h = 0;
    for (int t = 0; t < 16; t++) {
        float v = (h < 16) ? sd[w][lane][h] : FLT_BIG;
        int id   = (h < 16) ? si[w][lane][h] : 0;
        int src = lane;
#pragma unroll
        for (int off = 16; off; off >>= 1) {
            float vo = __shfl_xor_sync(0xffffffffu, v, off);
            int io = __shfl_xor_sync(0xffffffffu, id, off);
            int so = __shfl_xor_sync(0xffffffffu, src, off);
            if (vo < v || (vo == v && so < src)) { v = vo; id = io; src = so; }
        }
        if (lane == src) h++;
        if (lane == 0) g_idx[p * Kk + t] = id + (b << 12);   // GLOBAL index
        __syncwarp();
    }
}

// ---------------- kernel 2: q/k/v GEMMs with transposed output ----------------
__global__ __launch_bounds__(256) void k_qkv(const float* __restrict__ feats,
    const float* __restrict__ Wq, const float* __restrict__ bq,
    const float* __restrict__ Wk, const float* __restrict__ bk,
    const float* __restrict__ Wv, const float* __restrict__ bv) {
    const float* W; const float* bias; float* out;
    if (blockIdx.z == 0)      { W = Wq; bias = bq; out = g_qT; }
    else if (blockIdx.z == 1) { W = Wk; bias = bk; out = g_kT; }
    else                      { W = Wv; bias = bv; out = g_vT; }
    __shared__ float As[64 * 33], Ws[64 * 33];
    int tid = threadIdx.x;
    int p0 = blockIdx.x * 64;
    int b = p0 >> 12; int n0 = p0 & (Nn - 1);
    const float* fb = feats + b * Cc * Nn;
    int o0 = blockIdx.y * 64;
    int tx = tid & 15, ty = tid >> 4;
    float acc[4][4] = {};
    for (int k0 = 0; k0 < Cc; k0 += 32) {
        int e = tid * 8;
        int ppb = e & 63, kk = e >> 6;
        const float* src = fb + (k0 + kk) * Nn + n0 + ppb;
#pragma unroll
        for (int u = 0; u < 8; u++) As[(ppb + u) * 33 + kk] = src[u];
        int oo = tid >> 2, kb = (tid & 3) * 8;
        const float* wsrc = W + (o0 + oo) * Cc + k0 + kb;
#pragma unroll
        for (int u = 0; u < 8; u++) Ws[oo * 33 + kb + u] = wsrc[u];
        __syncthreads();
#pragma unroll 8
        for (int kq = 0; kq < 32; kq++) {
            float a[4], bb[4];
#pragma unroll
            for (int i = 0; i < 4; i++) a[i] = As[(ty + 16 * i) * 33 + kq];
#pragma unroll
            for (int j = 0; j < 4; j++) bb[j] = Ws[(tx + 16 * j) * 33 + kq];
#pragma unroll
            for (int i = 0; i < 4; i++)
#pragma unroll
                for (int j = 0; j < 4; j++) acc[i][j] = fmaf(a[i], bb[j], acc[i][j]);
        }
        __syncthreads();
    }
#pragma unroll
    for (int i = 0; i < 4; i++) {
        int p = p0 + ty + 16 * i;
#pragma unroll
        for (int j = 0; j < 4; j++) {
            int o = o0 + tx + 16 * j;
            out[p * Cc + o] = acc[i][j] + bias[o];
        }
    }
}

// ---------------- kernel 2b: feats transpose ----------------
__global__ void k_tr(const float* __restrict__ feats) {
    __shared__ float tile[32][33];
    int b = blockIdx.z;
    int n0 = blockIdx.x * 32, c0 = blockIdx.y * 32;
    int tx = threadIdx.x, ty = threadIdx.y;
#pragma unroll
    for (int r = 0; r < 32; r += 8)
        tile[ty + r][tx] = feats[b * Cc * Nn + (c0 + ty + r) * Nn + n0 + tx];
    __syncthreads();
#pragma unroll
    for (int r = 0; r < 32; r += 8)
        g_fT[((long)b * Nn + n0 + ty + r) * Cc + c0 + tx] = tile[tx][ty + r];
}

// ---------------- kernel 3: pass1 (geo MLP + rel conv -> t, BN stats) ----------------
// 8 points per block, J = 128 = 8*16 (point,neighbor) columns
__global__ __launch_bounds__(256) void k_pass1(const float* __restrict__ pts,
    const float* __restrict__ geo_W1, const float* __restrict__ geo_b1,
    const float* __restrict__ geo_W2, const float* __restrict__ geo_b2,
    const float* __restrict__ rel_W1, const float* __restrict__ rel_b1) {
    extern __shared__ float sm[];
    float* s_w   = sm;                  // 8192 (geo_W2 then rel_W1)
    float* s_g1  = s_w + 8192;          // [64][128]
    float* s_e   = s_g1 + 8192;         // [128][129]
    float* s_geo = s_e + 128 * 129;     // [3][128]
    float* s_sum = s_geo + 384;         // [64]
    float* s_ss  = s_sum + 64;          // [64]
    int*   s_idx = (int*)(s_ss + 64);   // [128]
    int tid = threadIdx.x;
    int p0 = blockIdx.x * 8;
    int b = p0 >> 12; int n0 = p0 & (Nn - 1);

    if (tid < 128) s_idx[tid] = g_idx[p0 * Kk + tid];
    for (int i = tid; i < 8192; i += 256) s_w[i] = geo_W2[i];
    __syncthreads();
    if (tid < 128) {
        int nb = s_idx[tid] & (Nn - 1);   // within-batch for pts
        int pl = tid >> 4;
        const float* pb = pts + b * 3 * Nn;
#pragma unroll
        for (int c = 0; c < 3; c++)
            s_geo[c * 128 + tid] = pb[c * Nn + n0 + pl] - pb[c * Nn + nb];
    }
    __syncthreads();
    // g1 = relu(geo_W1 @ rel_geo + b1)
    for (int idx = tid; idx < 8192; idx += 256) {
        int h = idx >> 7, j = idx & 127;
        float v = fmaf(geo_W1[h * 3 + 2], s_geo[256 + j],
                  fmaf(geo_W1[h * 3 + 1], s_geo[128 + j],
                  fmaf(geo_W1[h * 3 + 0], s_geo[j], geo_b1[h])));
        s_g1[idx] = fmaxf(v, 0.f);
    }
    __syncthreads();
    int tx = tid & 15, ty = tid >> 4;
    // geo_emb = geo_W2 @ g1 + b2   (128x128, k=64)
    {
        float acc[8][8] = {};
        for (int kk = 0; kk < 64; kk++) {
            float a[8], bb[8];
#pragma unroll
            for (int i = 0; i < 8; i++) a[i] = s_w[(ty + 16 * i) * 64 + kk];
#pragma unroll
            for (int j = 0; j < 8; j++) bb[j] = s_g1[kk * 128 + tx + 16 * j];
#pragma unroll
            for (int i = 0; i < 8; i++)
#pragma unroll
                for (int j = 0; j < 8; j++) acc[i][j] = fmaf(a[i], bb[j], acc[i][j]);
        }
#pragma unroll
        for (int i = 0; i < 8; i++) {
            int c = ty + 16 * i;
            float bc = geo_b2[c];
#pragma unroll
            for (int j = 0; j < 8; j++) s_e[c * 129 + tx + 16 * j] = acc[i][j] + bc;
        }
    }
    __syncthreads();
    // rel = q - knn_k + geo_emb (in place)
    {
        int c = tid & 127, jh = tid >> 7;
        for (int jo = 0; jo < 64; jo++) {
            int j = jo * 2 + jh;
            int pl = j >> 4;
            int nb = s_idx[j];                // GLOBAL index into g_kT
            s_e[c * 129 + j] += g_qT[(p0 + pl) * Cc + c] - g_kT[nb * Cc + c];
        }
    }
    __syncthreads();
    for (int i = tid; i < 8192; i += 256) s_w[i] = rel_W1[i];
    __syncthreads();
    // t = rel_W1 @ rel + b1  (64x128, k=128), write + BN partials
    {
        float acc[4][8] = {};
        for (int cc = 0; cc < 128; cc++) {
            float a[4], bb[8];
#pragma unroll
            for (int i = 0; i < 4; i++) a[i] = s_w[(ty + 16 * i) * 128 + cc];
#pragma unroll
            for (int j = 0; j < 8; j++) bb[j] = s_e[cc * 129 + tx + 16 * j];
#pragma unroll
            for (int i = 0; i < 4; i++)
#pragma unroll
                for (int j = 0; j < 8; j++) acc[i][j] = fmaf(a[i], bb[j], acc[i][j]);
        }
#pragma unroll
        for (int i = 0; i < 4; i++) {
            int h = ty + 16 * i;
            float bh = rel_b1[h];
            float rs = 0.f, rss = 0.f;
#pragma unroll
            for (int j = 0; j < 8; j++) {
                float v = acc[i][j] + bh;     // column j*16+tx -> point p0+j, k=tx
                g_t[(long)(p0 + j) * (Hh * Kk) + h * Kk + tx] = v;
                rs += v; rss += v * v;
            }
#pragma unroll
            for (int off = 8; off; off >>= 1) {
                rs  += __shfl_xor_sync(0xffffffffu, rs, off);
                rss += __shfl_xor_sync(0xffffffffu, rss, off);
            }
            if (tx == 0) { s_sum[h] = rs; s_ss[h] = rss; }
        }
    }
    __syncthreads();
    if (tid < 64) {
        atomicAdd(&g_bnsum[tid], (double)s_sum[tid]);
        atomicAdd(&g_bnss[tid],  (double)s_ss[tid]);
    }
}

// ---------------- kernel 4: BN finalize ----------------
__global__ void k_bnfin(const float* __restrict__ rel_g, const float* __restrict__ rel_beta) {
    int h = threadIdx.x;
    if (h >= Hh) return;
    double cnt = (double)Pp * Kk;
    double m = g_bnsum[h] / cnt;
    double var = g_bnss[h] / cnt - m * m;
    double inv = 1.0 / sqrt(var + 1e-5);
    double sc = (double)rel_g[h] * inv;
    g_bnscale[h] = (float)sc;
    g_bnshift[h] = (float)((double)rel_beta[h] - m * sc);
}

// ---------------- kernel 5: pass2 (attn + aggregation), 8 points/block ----------------
__global__ __launch_bounds__(256) void k_pass2(const float* __restrict__ pts,
    const float* __restrict__ geo_W1, const float* __restrict__ geo_b1,
    const float* __restrict__ geo_W2, const float* __restrict__ geo_b2,
    const float* __restrict__ rel_W2, const float* __restrict__ rel_b2) {
    extern __shared__ float sm[];
    float* s_w   = sm;                  // 8192 (geo_W2 then rel_W2)
    float* s_g1  = s_w + 8192;          // [64][128] (g1 then h2)
    float* s_e   = s_g1 + 8192;         // [128][129] geo_emb
    float* s_l   = s_e + 128 * 129;     // [128][129] logits/attn
    float* s_geo = s_l + 128 * 129;     // [3][128]
    int*   s_idx = (int*)(s_geo + 384); // [128]
    int tid = threadIdx.x;
    int p0 = blockIdx.x * 8;
    int b = p0 >> 12; int n0 = p0 & (Nn - 1);

    if (tid < 128) s_idx[tid] = g_idx[p0 * Kk + tid];
    for (int i = tid; i < 8192; i += 256) s_w[i] = geo_W2[i];
    __syncthreads();
    if (tid < 128) {
        int nb = s_idx[tid] & (Nn - 1);
        int pl = tid >> 4;
        const float* pb = pts + b * 3 * Nn;
#pragma unroll
        for (int c = 0; c < 3; c++)
            s_geo[c * 128 + tid] = pb[c * Nn + n0 + pl] - pb[c * Nn + nb];
    }
    __syncthreads();
    // g1 = relu(geo_W1 @ rel_geo + b1)
    for (int idx = tid; idx < 8192; idx += 256) {
        int h = idx >> 7, j = idx & 127;
        float v = fmaf(geo_W1[h * 3 + 2], s_geo[256 + j],
                  fmaf(geo_W1[h * 3 + 1], s_geo[128 + j],
                  fmaf(geo_W1[h * 3 + 0], s_geo[j], geo_b1[h])));
        s_g1[idx] = fmaxf(v, 0.f);
    }
    __syncthreads();
    int tx = tid & 15, ty = tid >> 4;
    // geo_emb = geo_W2 @ g1 + b2   (128x128, k=64)
    {
        float acc[8][8] = {};
        for (int kk = 0; kk < 64; kk++) {
            float a[8], bb[8];
#pragma unroll
            for (int i = 0; i < 8; i++) a[i] = s_w[(ty + 16 * i) * 64 + kk];
#pragma unroll
            for (int j = 0; j < 8; j++) bb[j] = s_g1[kk * 128 + tx + 16 * j];
#pragma unroll
            for (int i = 0; i < 8; i++)
#pragma unroll
                for (int j = 0; j < 8; j++) acc[i][j] = fmaf(a[i], bb[j], acc[i][j]);
        }
#pragma unroll
        for (int i = 0; i < 8; i++) {
            int c = ty + 16 * i;
            float bc = geo_b2[c];
#pragma unroll
            for (int j = 0; j < 8; j++) s_e[c * 129 + tx + 16 * j] = acc[i][j] + bc;
        }
    }
    __syncthreads();   // GEMM reads of s_g1 / s_w done
    // h2 = relu(BN(t)) into s_g1; also load rel_W2 into s_w
    for (int idx = tid; idx < 8192; idx += 256) {
        int h = idx >> 7, j = idx & 127;
        int pl = j >> 4, kki = j & 15;
        float tv = g_t[(long)(p0 + pl) * (Hh * Kk) + h * Kk + kki];
        s_g1[h * 128 + j] = fmaxf(fmaf(g_bnscale[h], tv, g_bnshift[h]), 0.f);
    }
    for (int i = tid; i < 8192; i += 256) s_w[i] = rel_W2[i];
    __syncthreads();
    // logits = rel_W2 @ h2 + b2   (128x128, k=64)
    {
        float acc[8][8] = {};
        for (int kk = 0; kk < 64; kk++) {
            float a[8], bb[8];
#pragma unroll
            for (int i = 0; i < 8; i++) a[i] = s_w[(ty + 16 * i) * 64 + kk];
#pragma unroll
            for (int j = 0; j < 8; j++) bb[j] = s_g1[kk * 128 + tx + 16 * j];
#pragma unroll
            for (int i = 0; i < 8; i++)
#pragma unroll
                for (int j = 0; j < 8; j++) acc[i][j] = fmaf(a[i], bb[j], acc[i][j]);
        }
#pragma unroll
        for (int i = 0; i < 8; i++) {
            int c = ty + 16 * i;
            float bc = rel_b2[c];
#pragma unroll
            for (int j = 0; j < 8; j++) s_l[c * 129 + tx + 16 * j] = acc[i][j] + bc;
        }
    }
    __syncthreads();
    // softmax over K per (c, point): 1024 rows of 16
    for (int r = tid; r < 1024; r += 256) {
        int c = r & 127, pl = r >> 7;
        float* row = s_l + c * 129 + pl * 16;
        float mx = row[0];
#pragma unroll
        for (int k = 1; k < 16; k++) mx = fmaxf(mx, row[k]);
        float ev[16]; float sum = 0.f;
#pragma unroll
        for (int k = 0; k < 16; k++) { ev[k] = __expf(row[k] - mx); sum += ev[k]; }
        float inv = 1.f / sum;
#pragma unroll
        for (int k = 0; k < 16; k++) row[k] = ev[k] * inv;
    }
    __syncthreads();
    // agg = sum_k attn * (v + geo_emb) + feats
    {
        int c = tid & 127, ph = tid >> 7;
        for (int pl = ph; pl < 8; pl += 2) {
            float acc = 0.f;
#pragma unroll
            for (int k = 0; k < 16; k++) {
                int j = pl * 16 + k;
                int nb = s_idx[j];            // GLOBAL index into g_vT
                acc = fmaf(s_l[c * 129 + j], g_vT[nb * Cc + c] + s_e[c * 129 + j], acc);
            }
            g_agg[(p0 + pl) * Cc + c] = acc + g_fT[(p0 + pl) * Cc + c];
        }
    }
}

// ---------------- kernel 6: out MLP layer 1 (relu), 128x128 tile, 8x8 ----------------
__global__ __launch_bounds__(256) void k_mlp1(const float* __restrict__ W, const float* __restrict__ bias) {
    __shared__ float As[128 * 33], Ws[128 * 33];
    int tid = threadIdx.x;
    int p0 = blockIdx.x * 128, o0 = blockIdx.y * 128;
    int tx = tid & 15, ty = tid >> 4;
    float acc[8][8] = {};
    for (int k0 = 0; k0 < Cc; k0 += 32) {
        int r = tid >> 1, kb = (tid & 1) * 16;
        const float* a = g_agg + (p0 + r) * Cc + k0 + kb;
#pragma unroll
        for (int u = 0; u < 16; u++) As[r * 33 + kb + u] = a[u];
        const float* wsrc = W + (o0 + r) * Cc + k0 + kb;
#pragma unroll
        for (int u = 0; u < 16; u++) Ws[r * 33 + kb + u] = wsrc[u];
        __syncthreads();
#pragma unroll 8
        for (int kk = 0; kk < 32; kk++) {
            float av[8], bv[8];
#pragma unroll
            for (int i = 0; i < 8; i++) av[i] = As[(ty + 16 * i) * 33 + kk];   // points
#pragma unroll
            for (int j = 0; j < 8; j++) bv[j] = Ws[(tx + 16 * j) * 33 + kk];   // outs
#pragma unroll
            for (int i = 0; i < 8; i++)
#pragma unroll
                for (int j = 0; j < 8; j++) acc[i][j] = fmaf(av[i], bv[j], acc[i][j]);
        }
        __syncthreads();
    }
#pragma unroll
    for (int i = 0; i < 8; i++) {
        int p = p0 + ty + 16 * i;
#pragma unroll
        for (int j = 0; j < 8; j++) {
            int o = o0 + tx + 16 * j;
            g_hid[p * (2 * Cc) + o] = fmaxf(acc[i][j] + bias[o], 0.f);
        }
    }
}

// ---------------- kernel 7: out MLP layer 2 + residual, 128x128 tile, 8x8 ----------------
__global__ __launch_bounds__(256) void k_mlp2(const float* __restrict__ W, const float* __restrict__ bias,
                                              float* __restrict__ out) {
    __shared__ float As[128 * 33], Ws[128 * 33];
    int tid = threadIdx.x;
    int p0 = blockIdx.x * 128;
    int tx = tid & 15, ty = tid >> 4;
    float acc[8][8] = {};   // i over outs, j over points
    for (int k0 = 0; k0 < 2 * Cc; k0 += 32) {
        int r = tid >> 1, kb = (tid & 1) * 16;
        const float* a = g_hid + (p0 + r) * (2 * Cc) + k0 + kb;
#pragma unroll
        for (int u = 0; u < 16; u++) As[r * 33 + kb + u] = a[u];
        const float* wsrc = W + r * (2 * Cc) + k0 + kb;   // 128 outs total
#pragma unroll
        for (int u = 0; u < 16; u++) Ws[r * 33 + kb + u] = wsrc[u];
        __syncthreads();
#pragma unroll 8
        for (int kk = 0; kk < 32; kk++) {
            float av[8], bv[8];
#pragma unroll
            for (int i = 0; i < 8; i++) av[i] = Ws[(ty + 16 * i) * 33 + kk];   // outs
#pragma unroll
            for (int j = 0; j < 8; j++) bv[j] = As[(tx + 16 * j) * 33 + kk];   // points
#pragma unroll
            for (int i = 0; i < 8; i++)
#pragma unroll
                for (int j = 0; j < 8; j++) acc[i][j] = fmaf(av[i], bv[j], acc[i][j]);
        }
        __syncthreads();
    }
#pragma unroll
    for (int i = 0; i < 8; i++) {
        int o = ty + 16 * i;
        float bo = bias[o];
#pragma unroll
        for (int j = 0; j < 8; j++) {
            int p = p0 + tx + 16 * j;
            int b = p >> 12, n = p & (Nn - 1);
            out[(long)b * Cc * Nn + o * Nn + n] = acc[i][j] + bo + g_agg[p * Cc + o];
        }
    }
}

// ---------------- launch ----------------
#define SMEM_P1 (33536 * 4)
#define SMEM_P2 (49920 * 4)

extern "C" void kernel_launch(void* const* d_in, const int* in_sizes, int n_in,
                              void* d_out, int out_size) {
    const float* pts   = (const float*)d_in[0];
    const float* feats = (const float*)d_in[1];
    const float* Wq = (const float*)d_in[2];  const float* bq = (const float*)d_in[3];
    const float* Wk = (const float*)d_in[4];  const float* bk = (const float*)d_in[5];
    const float* Wv = (const float*)d_in[6];  const float* bv = (const float*)d_in[7];
    const float* gW1 = (const float*)d_in[8]; const float* gb1 = (const float*)d_in[9];
    const float* gW2 = (const float*)d_in[10];const float* gb2 = (const float*)d_in[11];
    const float* rW1 = (const float*)d_in[12];const float* rb1 = (const float*)d_in[13];
    const float* rg  = (const float*)d_in[14];const float* rbe = (const float*)d_in[15];
    const float* rW2 = (const float*)d_in[16];const float* rb2 = (const float*)d_in[17];
    const float* oW1 = (const float*)d_in[18];const float* ob1 = (const float*)d_in[19];
    const float* oW2 = (const float*)d_in[20];const float* ob2 = (const float*)d_in[21];
    float* out = (float*)d_out;

    cudaFuncSetAttribute(k_pass1, cudaFuncAttributeMaxDynamicSharedMemorySize, SMEM_P1);
    cudaFuncSetAttribute(k_pass2, cudaFuncAttributeMaxDynamicSharedMemorySize, SMEM_P2);

    k_sq  <<<Pp / 256, 256>>>(pts);
    k_qkv <<<dim3(Pp / 64, 2, 3), 256>>>(feats, Wq, bq, Wk, bk, Wv, bv);
    k_tr  <<<dim3(Nn / 32, Cc / 32, Bn), dim3(32, 8)>>>(feats);
    k_knn <<<Pp / 8, 256>>>(pts);
    k_pass1<<<Pp / 8, 256, SMEM_P1>>>(pts, gW1, gb1, gW2, gb2, rW1, rb1);
    k_bnfin<<<1, 64>>>(rg, rbe);
    k_pass2<<<Pp / 8, 256, SMEM_P2>>>(pts, gW1, gb1, gW2, gb2, rW2, rb2);
    k_mlp1<<<dim3(Pp / 128, 2), 256>>>(oW1, ob1);
    k_mlp2<<<Pp / 128, 256>>>(oW2, ob2, out);
}

// round 6
// speedup vs baseline: 1.3072x; 1.0955x over previous
#include <cuda_runtime.h>
#include <math.h>

#define Bn 8
#define Cc 128
#define Nn 4096
#define Kk 16
#define Hh 64
#define Pp (Bn*Nn)          // 32768 points total
#define FLT_BIG 3.402823466e+38f

// ---------------- static device scratch (no allocations allowed) ----------------
__device__ float g_qT[Pp*Cc];        // q transposed  [P][C]
__device__ float g_kT[Pp*Cc];        // k transposed  [P][C]
__device__ float g_vT[Pp*Cc];        // v transposed  [P][C]
__device__ float g_fT[Pp*Cc];        // feats transposed [P][C]
__device__ float g_agg[Pp*Cc];       // aggregated features [P][C]
__device__ float g_hid[Pp*2*Cc];     // out-MLP hidden [P][2C]
__device__ float g_t[Pp*Hh*Kk];      // BN pre-activation [P][H][K]  (134MB)
__device__ int   g_idx[Pp*Kk];       // knn indices (GLOBAL point ids)
__device__ float g_sq[Pp];           // |pts|^2
__device__ double g_bnsum[Hh];
__device__ double g_bnss[Hh];
__device__ float g_bnscale[Hh];
__device__ float g_bnshift[Hh];

// ---------------- kernel 0: squared norms + zero BN accumulators ----------------
__global__ void k_sq(const float* __restrict__ pts) {
    int p = blockIdx.x * 256 + threadIdx.x;
    if (p < Hh) { g_bnsum[p] = 0.0; g_bnss[p] = 0.0; }
    if (p >= Pp) return;
    int b = p >> 12, n = p & (Nn - 1);
    const float* pb = pts + b * 3 * Nn;
    float x = pb[n], y = pb[Nn + n], z = pb[2 * Nn + n];
    g_sq[p] = x * x + y * y + z * z;
}

// ---------------- kernel 1: kNN — warp-collective top-16 with shared threshold ----------------
// Pool of 16 best (d, idx) lives in registers of lanes 0..15 (one entry per lane).
// tau is an upper bound on the pool max; candidates with d >= tau are rejected
// with zero extra work. Accepts (~90 per warp) are serialized warp-wide.
__global__ __launch_bounds__(256) void k_knn(const float* __restrict__ pts) {
    int w = threadIdx.x >> 5, lane = threadIdx.x & 31;
    int p = blockIdx.x * 8 + w;
    int b = p >> 12, n = p & (Nn - 1);
    const float* pb = pts + b * 3 * Nn;
    float qx = pb[n], qy = pb[Nn + n], qz = pb[2 * Nn + n];
    float sqn = g_sq[p];
    const float* sqb = g_sq + b * Nn;

    float pd = FLT_BIG;   // pool entry distance (valid on lanes 0..15)
    int   pi = 0;         // pool entry index
    float tau = FLT_BIG;  // upper bound on pool max

    for (int it = 0; it < Nn / 32; it++) {
        int m = it * 32 + lane;
        float px = pb[m], py = pb[Nn + m], pz = pb[2 * Nn + m];
        float inner = fmaf(qx, px, fmaf(qy, py, qz * pz));
        float d = sqn + sqb[m] - 2.0f * inner;
        unsigned mask = __ballot_sync(0xffffffffu, d < tau);
        while (mask) {
            int src = __ffs(mask) - 1;     // lowest lane first -> ascending m
            mask &= mask - 1;
            float ds = __shfl_sync(0xffffffffu, d, src);
            int   ms = __shfl_sync(0xffffffffu, m, src);
            // argmax over pool entries (lanes 0..15); evict larger index on ties
            float v = (lane < 16) ? pd : -FLT_BIG;
            int   vi = pi;
            int   L = lane;
#pragma unroll
            for (int off = 8; off; off >>= 1) {
                float vo = __shfl_xor_sync(0xffffffffu, v, off);
                int vio = __shfl_xor_sync(0xffffffffu, vi, off);
                int Lo  = __shfl_xor_sync(0xffffffffu, L, off);
                if (vo > v || (vo == v && vio > vi)) { v = vo; vi = vio; L = Lo; }
            }
            v = __shfl_sync(0xffffffffu, v, 0);
            L = __shfl_sync(0xffffffffu, L, 0);
            if (ds < v) {                  // strict: equal keeps older (lower index)
                if (lane == L) { pd = ds; pi = ms; }
                tau = v;                   // pre-replacement max: stale-safe bound
            }
        }
    }
    if (lane < 16) g_idx[p * Kk + lane] = pi + (b << 12);   // GLOBAL index; K-order arbitrary
}

// ---------------- kernel 2: q/k/v GEMMs with transposed output ----------------
__global__ __launch_bounds__(256) void k_qkv(const float* __restrict__ feats,
    const float* __restrict__ Wq, const float* __restrict__ bq,
    const float* __restrict__ Wk, const float* __restrict__ bk,
    const float* __restrict__ Wv, const float* __restrict__ bv) {
    const float* W; const float* bias; float* out;
    if (blockIdx.z == 0)      { W = Wq; bias = bq; out = g_qT; }
    else if (blockIdx.z == 1) { W = Wk; bias = bk; out = g_kT; }
    else                      { W = Wv; bias = bv; out = g_vT; }
    __shared__ float As[64 * 33], Ws[64 * 33];
    int tid = threadIdx.x;
    int p0 = blockIdx.x * 64;
    int b = p0 >> 12; int n0 = p0 & (Nn - 1);
    const float* fb = feats + b * Cc * Nn;
    int o0 = blockIdx.y * 64;
    int tx = tid & 15, ty = tid >> 4;
    float acc[4][4] = {};
    for (int k0 = 0; k0 < Cc; k0 += 32) {
        int e = tid * 8;
        int ppb = e & 63, kk = e >> 6;
        const float* src = fb + (k0 + kk) * Nn + n0 + ppb;
#pragma unroll
        for (int u = 0; u < 8; u++) As[(ppb + u) * 33 + kk] = src[u];
        int oo = tid >> 2, kb = (tid & 3) * 8;
        const float* wsrc = W + (o0 + oo) * Cc + k0 + kb;
#pragma unroll
        for (int u = 0; u < 8; u++) Ws[oo * 33 + kb + u] = wsrc[u];
        __syncthreads();
#pragma unroll 8
        for (int kq = 0; kq < 32; kq++) {
            float a[4], bb[4];
#pragma unroll
            for (int i = 0; i < 4; i++) a[i] = As[(ty + 16 * i) * 33 + kq];
#pragma unroll
            for (int j = 0; j < 4; j++) bb[j] = Ws[(tx + 16 * j) * 33 + kq];
#pragma unroll
            for (int i = 0; i < 4; i++)
#pragma unroll
                for (int j = 0; j < 4; j++) acc[i][j] = fmaf(a[i], bb[j], acc[i][j]);
        }
        __syncthreads();
    }
#pragma unroll
    for (int i = 0; i < 4; i++) {
        int p = p0 + ty + 16 * i;
#pragma unroll
        for (int j = 0; j < 4; j++) {
            int o = o0 + tx + 16 * j;
            out[p * Cc + o] = acc[i][j] + bias[o];
        }
    }
}

// ---------------- kernel 2b: feats transpose ----------------
__global__ void k_tr(const float* __restrict__ feats) {
    __shared__ float tile[32][33];
    int b = blockIdx.z;
    int n0 = blockIdx.x * 32, c0 = blockIdx.y * 32;
    int tx = threadIdx.x, ty = threadIdx.y;
#pragma unroll
    for (int r = 0; r < 32; r += 8)
        tile[ty + r][tx] = feats[b * Cc * Nn + (c0 + ty + r) * Nn + n0 + tx];
    __syncthreads();
#pragma unroll
    for (int r = 0; r < 32; r += 8)
        g_fT[((long)b * Nn + n0 + ty + r) * Cc + c0 + tx] = tile[tx][ty + r];
}

// ---------------- kernel 3: pass1 (geo MLP + rel conv -> t, BN stats) ----------------
// 8 points per block, J = 128 = 8*16 (point,neighbor) columns
__global__ __launch_bounds__(256) void k_pass1(const float* __restrict__ pts,
    const float* __restrict__ geo_W1, const float* __restrict__ geo_b1,
    const float* __restrict__ geo_W2, const float* __restrict__ geo_b2,
    const float* __restrict__ rel_W1, const float* __restrict__ rel_b1) {
    extern __shared__ float sm[];
    float* s_w   = sm;                  // 8192 (geo_W2 then rel_W1)
    float* s_g1  = s_w + 8192;          // [64][128]
    float* s_e   = s_g1 + 8192;         // [128][129]
    float* s_geo = s_e + 128 * 129;     // [3][128]
    float* s_sum = s_geo + 384;         // [64]
    float* s_ss  = s_sum + 64;          // [64]
    int*   s_idx = (int*)(s_ss + 64);   // [128]
    int tid = threadIdx.x;
    int p0 = blockIdx.x * 8;
    int b = p0 >> 12; int n0 = p0 & (Nn - 1);

    if (tid < 128) s_idx[tid] = g_idx[p0 * Kk + tid];
    for (int i = tid; i < 8192; i += 256) s_w[i] = geo_W2[i];
    __syncthreads();
    if (tid < 128) {
        int nb = s_idx[tid] & (Nn - 1);   // within-batch for pts
        int pl = tid >> 4;
        const float* pb = pts + b * 3 * Nn;
#pragma unroll
        for (int c = 0; c < 3; c++)
            s_geo[c * 128 + tid] = pb[c * Nn + n0 + pl] - pb[c * Nn + nb];
    }
    __syncthreads();
    // g1 = relu(geo_W1 @ rel_geo + b1)
    for (int idx = tid; idx < 8192; idx += 256) {
        int h = idx >> 7, j = idx & 127;
        float v = fmaf(geo_W1[h * 3 + 2], s_geo[256 + j],
                  fmaf(geo_W1[h * 3 + 1], s_geo[128 + j],
                  fmaf(geo_W1[h * 3 + 0], s_geo[j], geo_b1[h])));
        s_g1[idx] = fmaxf(v, 0.f);
    }
    __syncthreads();
    int tx = tid & 15, ty = tid >> 4;
    // geo_emb = geo_W2 @ g1 + b2   (128x128, k=64)
    {
        float acc[8][8] = {};
        for (int kk = 0; kk < 64; kk++) {
            float a[8], bb[8];
#pragma unroll
            for (int i = 0; i < 8; i++) a[i] = s_w[(ty + 16 * i) * 64 + kk];
#pragma unroll
            for (int j = 0; j < 8; j++) bb[j] = s_g1[kk * 128 + tx + 16 * j];
#pragma unroll
            for (int i = 0; i < 8; i++)
#pragma unroll
                for (int j = 0; j < 8; j++) acc[i][j] = fmaf(a[i], bb[j], acc[i][j]);
        }
#pragma unroll
        for (int i = 0; i < 8; i++) {
            int c = ty + 16 * i;
            float bc = geo_b2[c];
#pragma unroll
            for (int j = 0; j < 8; j++) s_e[c * 129 + tx + 16 * j] = acc[i][j] + bc;
        }
    }
    __syncthreads();
    // rel = q - knn_k + geo_emb (in place)
    {
        int c = tid & 127, jh = tid >> 7;
        for (int jo = 0; jo < 64; jo++) {
            int j = jo * 2 + jh;
            int pl = j >> 4;
            int nb = s_idx[j];                // GLOBAL index into g_kT
            s_e[c * 129 + j] += g_qT[(p0 + pl) * Cc + c] - g_kT[nb * Cc + c];
        }
    }
    __syncthreads();
    for (int i = tid; i < 8192; i += 256) s_w[i] = rel_W1[i];
    __syncthreads();
    // t = rel_W1 @ rel + b1  (64x128, k=128), write + BN partials
    {
        float acc[4][8] = {};
        for (int cc = 0; cc < 128; cc++) {
            float a[4], bb[8];
#pragma unroll
            for (int i = 0; i < 4; i++) a[i] = s_w[(ty + 16 * i) * 128 + cc];
#pragma unroll
            for (int j = 0; j < 8; j++) bb[j] = s_e[cc * 129 + tx + 16 * j];
#pragma unroll
            for (int i = 0; i < 4; i++)
#pragma unroll
                for (int j = 0; j < 8; j++) acc[i][j] = fmaf(a[i], bb[j], acc[i][j]);
        }
#pragma unroll
        for (int i = 0; i < 4; i++) {
            int h = ty + 16 * i;
            float bh = rel_b1[h];
            float rs = 0.f, rss = 0.f;
#pragma unroll
            for (int j = 0; j < 8; j++) {
                float v = acc[i][j] + bh;     // column j*16+tx -> point p0+j, k=tx
                g_t[(long)(p0 + j) * (Hh * Kk) + h * Kk + tx] = v;
                rs += v; rss += v * v;
            }
#pragma unroll
            for (int off = 8; off; off >>= 1) {
                rs  += __shfl_xor_sync(0xffffffffu, rs, off);
                rss += __shfl_xor_sync(0xffffffffu, rss, off);
            }
            if (tx == 0) { s_sum[h] = rs; s_ss[h] = rss; }
        }
    }
    __syncthreads();
    if (tid < 64) {
        atomicAdd(&g_bnsum[tid], (double)s_sum[tid]);
        atomicAdd(&g_bnss[tid],  (double)s_ss[tid]);
    }
}

// ---------------- kernel 4: BN finalize ----------------
__global__ void k_bnfin(const float* __restrict__ rel_g, const float* __restrict__ rel_beta) {
    int h = threadIdx.x;
    if (h >= Hh) return;
    double cnt = (double)Pp * Kk;
    double m = g_bnsum[h] / cnt;
    double var = g_bnss[h] / cnt - m * m;
    double inv = 1.0 / sqrt(var + 1e-5);
    double sc = (double)rel_g[h] * inv;
    g_bnscale[h] = (float)sc;
    g_bnshift[h] = (float)((double)rel_beta[h] - m * sc);
}

// ---------------- kernel 5: pass2 (attn + aggregation), 8 points/block ----------------
__global__ __launch_bounds__(256) void k_pass2(const float* __restrict__ pts,
    const float* __restrict__ geo_W1, const float* __restrict__ geo_b1,
    const float* __restrict__ geo_W2, const float* __restrict__ geo_b2,
    const float* __restrict__ rel_W2, const float* __restrict__ rel_b2) {
    extern __shared__ float sm[];
    float* s_w   = sm;                  // 8192 (geo_W2 then rel_W2)
    float* s_g1  = s_w + 8192;          // [64][128] (g1 then h2)
    float* s_e   = s_g1 + 8192;         // [128][129] geo_emb
    float* s_l   = s_e + 128 * 129;     // [128][129] logits/attn
    float* s_geo = s_l + 128 * 129;     // [3][128]
    int*   s_idx = (int*)(s_geo + 384); // [128]
    int tid = threadIdx.x;
    int p0 = blockIdx.x * 8;
    int b = p0 >> 12; int n0 = p0 & (Nn - 1);

    if (tid < 128) s_idx[tid] = g_idx[p0 * Kk + tid];
    for (int i = tid; i < 8192; i += 256) s_w[i] = geo_W2[i];
    __syncthreads();
    if (tid < 128) {
        int nb = s_idx[tid] & (Nn - 1);
        int pl = tid >> 4;
        const float* pb = pts + b * 3 * Nn;
#pragma unroll
        for (int c = 0; c < 3; c++)
            s_geo[c * 128 + tid] = pb[c * Nn + n0 + pl] - pb[c * Nn + nb];
    }
    __syncthreads();
    // g1 = relu(geo_W1 @ rel_geo + b1)
    for (int idx = tid; idx < 8192; idx += 256) {
        int h = idx >> 7, j = idx & 127;
        float v = fmaf(geo_W1[h * 3 + 2], s_geo[256 + j],
                  fmaf(geo_W1[h * 3 + 1], s_geo[128 + j],
                  fmaf(geo_W1[h * 3 + 0], s_geo[j], geo_b1[h])));
        s_g1[idx] = fmaxf(v, 0.f);
    }
    __syncthreads();
    int tx = tid & 15, ty = tid >> 4;
    // geo_emb = geo_W2 @ g1 + b2   (128x128, k=64)
    {
        float acc[8][8] = {};
        for (int kk = 0; kk < 64; kk++) {
            float a[8], bb[8];
#pragma unroll
            for (int i = 0; i < 8; i++) a[i] = s_w[(ty + 16 * i) * 64 + kk];
#pragma unroll
            for (int j = 0; j < 8; j++) bb[j] = s_g1[kk * 128 + tx + 16 * j];
#pragma unroll
            for (int i = 0; i < 8; i++)
#pragma unroll
                for (int j = 0; j < 8; j++) acc[i][j] = fmaf(a[i], bb[j], acc[i][j]);
        }
#pragma unroll
        for (int i = 0; i < 8; i++) {
            int c = ty + 16 * i;
            float bc = geo_b2[c];
#pragma unroll
            for (int j = 0; j < 8; j++) s_e[c * 129 + tx + 16 * j] = acc[i][j] + bc;
        }
    }
    __syncthreads();   // GEMM reads of s_g1 / s_w done
    // h2 = relu(BN(t)) into s_g1; also load rel_W2 into s_w
    for (int idx = tid; idx < 8192; idx += 256) {
        int h = idx >> 7, j = idx & 127;
        int pl = j >> 4, kki = j & 15;
        float tv = g_t[(long)(p0 + pl) * (Hh * Kk) + h * Kk + kki];
        s_g1[h * 128 + j] = fmaxf(fmaf(g_bnscale[h], tv, g_bnshift[h]), 0.f);
    }
    for (int i = tid; i < 8192; i += 256) s_w[i] = rel_W2[i];
    __syncthreads();
    // logits = rel_W2 @ h2 + b2   (128x128, k=64)
    {
        float acc[8][8] = {};
        for (int kk = 0; kk < 64; kk++) {
            float a[8], bb[8];
#pragma unroll
            for (int i = 0; i < 8; i++) a[i] = s_w[(ty + 16 * i) * 64 + kk];
#pragma unroll
            for (int j = 0; j < 8; j++) bb[j] = s_g1[kk * 128 + tx + 16 * j];
#pragma unroll
            for (int i = 0; i < 8; i++)
#pragma unroll
                for (int j = 0; j < 8; j++) acc[i][j] = fmaf(a[i], bb[j], acc[i][j]);
        }
#pragma unroll
        for (int i = 0; i < 8; i++) {
            int c = ty + 16 * i;
            float bc = rel_b2[c];
#pragma unroll
            for (int j = 0; j < 8; j++) s_l[c * 129 + tx + 16 * j] = acc[i][j] + bc;
        }
    }
    __syncthreads();
    // softmax over K per (c, point): 1024 rows of 16
    for (int r = tid; r < 1024; r += 256) {
        int c = r & 127, pl = r >> 7;
        float* row = s_l + c * 129 + pl * 16;
        float mx = row[0];
#pragma unroll
        for (int k = 1; k < 16; k++) mx = fmaxf(mx, row[k]);
        float ev[16]; float sum = 0.f;
#pragma unroll
        for (int k = 0; k < 16; k++) { ev[k] = __expf(row[k] - mx); sum += ev[k]; }
        float inv = 1.f / sum;
#pragma unroll
        for (int k = 0; k < 16; k++) row[k] = ev[k] * inv;
    }
    __syncthreads();
    // agg = sum_k attn * (v + geo_emb) + feats
    {
        int c = tid & 127, ph = tid >> 7;
        for (int pl = ph; pl < 8; pl += 2) {
            float acc = 0.f;
#pragma unroll
            for (int k = 0; k < 16; k++) {
                int j = pl * 16 + k;
                int nb = s_idx[j];            // GLOBAL index into g_vT
                acc = fmaf(s_l[c * 129 + j], g_vT[nb * Cc + c] + s_e[c * 129 + j], acc);
            }
            g_agg[(p0 + pl) * Cc + c] = acc + g_fT[(p0 + pl) * Cc + c];
        }
    }
}

// ---------------- kernel 6: out MLP layer 1 (relu), 128x128 tile, 8x8 ----------------
__global__ __launch_bounds__(256) void k_mlp1(const float* __restrict__ W, const float* __restrict__ bias) {
    __shared__ float As[128 * 33], Ws[128 * 33];
    int tid = threadIdx.x;
    int p0 = blockIdx.x * 128, o0 = blockIdx.y * 128;
    int tx = tid & 15, ty = tid >> 4;
    float acc[8][8] = {};
    for (int k0 = 0; k0 < Cc; k0 += 32) {
        int r = tid >> 1, kb = (tid & 1) * 16;
        const float* a = g_agg + (p0 + r) * Cc + k0 + kb;
#pragma unroll
        for (int u = 0; u < 16; u++) As[r * 33 + kb + u] = a[u];
        const float* wsrc = W + (o0 + r) * Cc + k0 + kb;
#pragma unroll
        for (int u = 0; u < 16; u++) Ws[r * 33 + kb + u] = wsrc[u];
        __syncthreads();
#pragma unroll 8
        for (int kk = 0; kk < 32; kk++) {
            float av[8], bv[8];
#pragma unroll
            for (int i = 0; i < 8; i++) av[i] = As[(ty + 16 * i) * 33 + kk];   // points
#pragma unroll
            for (int j = 0; j < 8; j++) bv[j] = Ws[(tx + 16 * j) * 33 + kk];   // outs
#pragma unroll
            for (int i = 0; i < 8; i++)
#pragma unroll
                for (int j = 0; j < 8; j++) acc[i][j] = fmaf(av[i], bv[j], acc[i][j]);
        }
        __syncthreads();
    }
#pragma unroll
    for (int i = 0; i < 8; i++) {
        int p = p0 + ty + 16 * i;
#pragma unroll
        for (int j = 0; j < 8; j++) {
            int o = o0 + tx + 16 * j;
            g_hid[p * (2 * Cc) + o] = fmaxf(acc[i][j] + bias[o], 0.f);
        }
    }
}

// ---------------- kernel 7: out MLP layer 2 + residual, 128x128 tile, 8x8 ----------------
__global__ __launch_bounds__(256) void k_mlp2(const float* __restrict__ W, const float* __restrict__ bias,
                                              float* __restrict__ out) {
    __shared__ float As[128 * 33], Ws[128 * 33];
    int tid = threadIdx.x;
    int p0 = blockIdx.x * 128;
    int tx = tid & 15, ty = tid >> 4;
    float acc[8][8] = {};   // i over outs, j over points
    for (int k0 = 0; k0 < 2 * Cc; k0 += 32) {
        int r = tid >> 1, kb = (tid & 1) * 16;
        const float* a = g_hid + (p0 + r) * (2 * Cc) + k0 + kb;
#pragma unroll
        for (int u = 0; u < 16; u++) As[r * 33 + kb + u] = a[u];
        const float* wsrc = W + r * (2 * Cc) + k0 + kb;   // 128 outs total
#pragma unroll
        for (int u = 0; u < 16; u++) Ws[r * 33 + kb + u] = wsrc[u];
        __syncthreads();
#pragma unroll 8
        for (int kk = 0; kk < 32; kk++) {
            float av[8], bv[8];
#pragma unroll
            for (int i = 0; i < 8; i++) av[i] = Ws[(ty + 16 * i) * 33 + kk];   // outs
#pragma unroll
            for (int j = 0; j < 8; j++) bv[j] = As[(tx + 16 * j) * 33 + kk];   // points
#pragma unroll
            for (int i = 0; i < 8; i++)
#pragma unroll
                for (int j = 0; j < 8; j++) acc[i][j] = fmaf(av[i], bv[j], acc[i][j]);
        }
        __syncthreads();
    }
#pragma unroll
    for (int i = 0; i < 8; i++) {
        int o = ty + 16 * i;
        float bo = bias[o];
#pragma unroll
        for (int j = 0; j < 8; j++) {
            int p = p0 + tx + 16 * j;
            int b = p >> 12, n = p & (Nn - 1);
            out[(long)b * Cc * Nn + o * Nn + n] = acc[i][j] + bo + g_agg[p * Cc + o];
        }
    }
}

// ---------------- launch ----------------
#define SMEM_P1 (33536 * 4)
#define SMEM_P2 (49920 * 4)

extern "C" void kernel_launch(void* const* d_in, const int* in_sizes, int n_in,
                              void* d_out, int out_size) {
    const float* pts   = (const float*)d_in[0];
    const float* feats = (const float*)d_in[1];
    const float* Wq = (const float*)d_in[2];  const float* bq = (const float*)d_in[3];
    const float* Wk = (const float*)d_in[4];  const float* bk = (const float*)d_in[5];
    const float* Wv = (const float*)d_in[6];  const float* bv = (const float*)d_in[7];
    const float* gW1 = (const float*)d_in[8]; const float* gb1 = (const float*)d_in[9];
    const float* gW2 = (const float*)d_in[10];const float* gb2 = (const float*)d_in[11];
    const float* rW1 = (const float*)d_in[12];const float* rb1 = (const float*)d_in[13];
    const float* rg  = (const float*)d_in[14];const float* rbe = (const float*)d_in[15];
    const float* rW2 = (const float*)d_in[16];const float* rb2 = (const float*)d_in[17];
    const float* oW1 = (const float*)d_in[18];const float* ob1 = (const float*)d_in[19];
    const float* oW2 = (const float*)d_in[20];const float* ob2 = (const float*)d_in[21];
    float* out = (float*)d_out;

    cudaFuncSetAttribute(k_pass1, cudaFuncAttributeMaxDynamicSharedMemorySize, SMEM_P1);
    cudaFuncSetAttribute(k_pass2, cudaFuncAttributeMaxDynamicSharedMemorySize, SMEM_P2);

    k_sq  <<<Pp / 256, 256>>>(pts);
    k_qkv <<<dim3(Pp / 64, 2, 3), 256>>>(feats, Wq, bq, Wk, bk, Wv, bv);
    k_tr  <<<dim3(Nn / 32, Cc / 32, Bn), dim3(32, 8)>>>(feats);
    k_knn <<<Pp / 8, 256>>>(pts);
    k_pass1<<<Pp / 8, 256, SMEM_P1>>>(pts, gW1, gb1, gW2, gb2, rW1, rb1);
    k_bnfin<<<1, 64>>>(rg, rbe);
    k_pass2<<<Pp / 8, 256, SMEM_P2>>>(pts, gW1, gb1, gW2, gb2, rW2, rb2);
    k_mlp1<<<dim3(Pp / 128, 2), 256>>>(oW1, ob1);
    k_mlp2<<<Pp / 128, 256>>>(oW2, ob2, out);
}

// round 8
// speedup vs baseline: 1.3896x; 1.0630x over previous
#include <cuda_runtime.h>
#include <math.h>

#define Bn 8
#define Cc 128
#define Nn 4096
#define Kk 16
#define Hh 64
#define Pp (Bn*Nn)          // 32768 points total
#define FLT_BIG 3.402823466e+38f

// ---------------- static device scratch (no allocations allowed) ----------------
__device__ float g_qT[Pp*Cc];        // q transposed  [P][C]
__device__ float g_kT[Pp*Cc];        // k transposed  [P][C]
__device__ float g_vT[Pp*Cc];        // v transposed  [P][C]
__device__ float g_fT[Pp*Cc];        // feats transposed [P][C]
__device__ float g_agg[Pp*Cc];       // aggregated features [P][C]
__device__ float g_hid[Pp*2*Cc];     // out-MLP hidden [P][2C]
__device__ float g_t[Pp*Hh*Kk];      // BN pre-activation [P][H][K]  (134MB)
__device__ int   g_idx[Pp*Kk];       // knn indices (GLOBAL point ids)
__device__ float g_sq[Pp];           // |pts|^2
__device__ double g_bnsum[Hh];
__device__ double g_bnss[Hh];
__device__ float g_bnscale[Hh];
__device__ float g_bnshift[Hh];

// ---------------- kernel 0: squared norms + zero BN accumulators ----------------
__global__ void k_sq(const float* __restrict__ pts) {
    int p = blockIdx.x * 256 + threadIdx.x;
    if (p < Hh) { g_bnsum[p] = 0.0; g_bnss[p] = 0.0; }
    if (p >= Pp) return;
    int b = p >> 12, n = p & (Nn - 1);
    const float* pb = pts + b * 3 * Nn;
    float x = pb[n], y = pb[Nn + n], z = pb[2 * Nn + n];
    g_sq[p] = x * x + y * y + z * z;
}

// ---------------- kernel 1: kNN — exact bound-then-verify top-16 ----------------
// Phase 1: per-lane top-2 (registers) -> 64 candidates; tau = 16th lex-smallest
//          of those 64 (a VALID upper bound on the true 16th distance).
// Phase 2: rescan, compact all d <= tau into smem (ballot prefix, no serialization).
// Phase 3: 16 exact lex-(d, index) argmin rounds -> reference-identical selection.
__global__ __launch_bounds__(256) void k_knn(const float* __restrict__ pts) {
    __shared__ float s_d[8][64];
    __shared__ int   s_i[8][64];
    int w = threadIdx.x >> 5, lane = threadIdx.x & 31;
    int p = blockIdx.x * 8 + w;
    int b = p >> 12, n = p & (Nn - 1);
    const float* pb = pts + b * 3 * Nn;
    float qx = pb[n], qy = pb[Nn + n], qz = pb[2 * Nn + n];
    float sqn = g_sq[p];
    const float* sqb = g_sq + b * Nn;

    // ---- phase 1: per-lane top-2 ----
    float d0 = FLT_BIG, d1 = FLT_BIG; int i0 = 0, i1 = 0;
    for (int it = 0; it < Nn / 32; it++) {
        int m = it * 32 + lane;
        float px = pb[m], py = pb[Nn + m], pz = pb[2 * Nn + m];
        float inner = fmaf(qx, px, fmaf(qy, py, qz * pz));
        float d = sqn + sqb[m] - 2.0f * inner;
        if (d < d1) {
            if (d < d0) { d1 = d0; i1 = i0; d0 = d; i0 = m; }
            else        { d1 = d;  i1 = m; }
        }
    }
    // tau = 16th lex-smallest of the 64 (2 per lane)
    float tau = FLT_BIG;
    {
        float e0 = d0, e1 = d1; int j0 = i0, j1 = i1;
        for (int r = 0; r < 16; r++) {
            float v; int vi, sel;
            if (e0 < e1 || (e0 == e1 && j0 < j1)) { v = e0; vi = j0; sel = 0; }
            else                                   { v = e1; vi = j1; sel = 1; }
            float bv = v; int bvi = vi, bl = lane;
#pragma unroll
            for (int off = 16; off; off >>= 1) {
                float vo = __shfl_xor_sync(0xffffffffu, bv, off);
                int vio = __shfl_xor_sync(0xffffffffu, bvi, off);
                int lo  = __shfl_xor_sync(0xffffffffu, bl, off);
                if (vo < bv || (vo == bv && vio < bvi)) { bv = vo; bvi = vio; bl = lo; }
            }
            if (lane == bl) { if (sel == 0) e0 = FLT_BIG; else e1 = FLT_BIG; }
            tau = bv;   // after round 15: 16th lex-smallest value
        }
    }

    // ---- phase 2: compact all d <= tau ----
    int cnt = 0;
    for (int it = 0; it < Nn / 32; it++) {
        int m = it * 32 + lane;
        float px = pb[m], py = pb[Nn + m], pz = pb[2 * Nn + m];
        float inner = fmaf(qx, px, fmaf(qy, py, qz * pz));
        float d = sqn + sqb[m] - 2.0f * inner;
        bool acc = (d <= tau);
        unsigned msk = __ballot_sync(0xffffffffu, acc);
        if (acc) {
            int pos = cnt + __popc(msk & ((1u << lane) - 1u));
            if (pos < 64) { s_d[w][pos] = d; s_i[w][pos] = m; }
        }
        cnt += __popc(msk);
    }
    __syncwarp();
    int S = (cnt < 64) ? cnt : 64;

    // ---- phase 3: exact 16 smallest with (d, index) lex order ----
    float da = (lane < S)      ? s_d[w][lane]      : FLT_BIG;
    int   ia = (lane < S)      ? s_i[w][lane]      : 0x7fffffff;
    float db = (lane + 32 < S) ? s_d[w][lane + 32] : FLT_BIG;
    int   ib = (lane + 32 < S) ? s_i[w][lane + 32] : 0x7fffffff;
    for (int r = 0; r < 16; r++) {
        float v; int vi, sel;
        if (da < db || (da == db && ia < ib)) { v = da; vi = ia; sel = 0; }
        else                                   { v = db; vi = ib; sel = 1; }
        float bv = v; int bvi = vi, bl = lane;
#pragma unroll
        for (int off = 16; off; off >>= 1) {
            float vo = __shfl_xor_sync(0xffffffffu, bv, off);
            int vio = __shfl_xor_sync(0xffffffffu, bvi, off);
            int lo  = __shfl_xor_sync(0xffffffffu, bl, off);
            if (vo < bv || (vo == bv && vio < bvi)) { bv = vo; bvi = vio; bl = lo; }
        }
        if (lane == bl) {
            if (sel == 0) { da = FLT_BIG; ia = 0x7fffffff; }
            else          { db = FLT_BIG; ib = 0x7fffffff; }
        }
        if (lane == 0) g_idx[p * Kk + r] = bvi + (b << 12);   // GLOBAL index
    }
}

// ---------------- kernel 2: q/k/v GEMMs (128x128 tile, 8x8), folds feats transpose ----------------
__global__ __launch_bounds__(256) void k_qkv(const float* __restrict__ feats,
    const float* __restrict__ Wq, const float* __restrict__ bq,
    const float* __restrict__ Wk, const float* __restrict__ bk,
    const float* __restrict__ Wv, const float* __restrict__ bv) {
    const float* W; const float* bias; float* out;
    if (blockIdx.z == 0)      { W = Wq; bias = bq; out = g_qT; }
    else if (blockIdx.z == 1) { W = Wk; bias = bk; out = g_kT; }
    else                      { W = Wv; bias = bv; out = g_vT; }
    __shared__ float As[32 * 129];   // k-major: As[cc][nn]
    __shared__ float Ws[128 * 33];   // Ws[o][kk]
    int tid = threadIdx.x;
    int p0 = blockIdx.x * 128;
    int b = p0 >> 12, n0 = p0 & (Nn - 1);
    const float* fb = feats + b * Cc * Nn;
    int tx = tid & 15, ty = tid >> 4;
    float acc[8][8] = {};
    for (int k0 = 0; k0 < Cc; k0 += 32) {
        {   // coalesced load of feats chunk [32 k][128 n]
            int cc = tid >> 3;            // 0..31
            int nn0 = (tid & 7) * 16;     // 0..112
            const float* src = fb + (k0 + cc) * Nn + n0 + nn0;
#pragma unroll
            for (int u = 0; u < 16; u++) As[cc * 129 + nn0 + u] = src[u];
        }
        {
            int r = tid >> 1, kb = (tid & 1) * 16;
            const float* wsrc = W + r * Cc + k0 + kb;
#pragma unroll
            for (int u = 0; u < 16; u++) Ws[r * 33 + kb + u] = wsrc[u];
        }
        __syncthreads();
        if (blockIdx.z == 0) {   // fold feats transpose: g_fT[p][c]
            int r = tid >> 1, kb = (tid & 1) * 16;
            float* dst = g_fT + (long)(p0 + r) * Cc + k0 + kb;
#pragma unroll
            for (int u = 0; u < 16; u++) dst[u] = As[(kb + u) * 129 + r];
        }
#pragma unroll 8
        for (int kk = 0; kk < 32; kk++) {
            float av[8], bvv[8];
#pragma unroll
            for (int i = 0; i < 8; i++) av[i] = As[kk * 129 + ty + 16 * i];   // points
#pragma unroll
            for (int j = 0; j < 8; j++) bvv[j] = Ws[(tx + 16 * j) * 33 + kk]; // outs
#pragma unroll
            for (int i = 0; i < 8; i++)
#pragma unroll
                for (int j = 0; j < 8; j++) acc[i][j] = fmaf(av[i], bvv[j], acc[i][j]);
        }
        __syncthreads();
    }
#pragma unroll
    for (int i = 0; i < 8; i++) {
        int pp = p0 + ty + 16 * i;
#pragma unroll
        for (int j = 0; j < 8; j++) {
            int o = tx + 16 * j;
            out[(long)pp * Cc + o] = acc[i][j] + bias[o];
        }
    }
}

// ---------------- kernel 3: pass1 (geo MLP + rel conv -> t, BN stats) ----------------
// 8 points per block, J = 128 = 8*16 (point,neighbor) columns
__global__ __launch_bounds__(256) void k_pass1(const float* __restrict__ pts,
    const float* __restrict__ geo_W1, const float* __restrict__ geo_b1,
    const float* __restrict__ geo_W2, const float* __restrict__ geo_b2,
    const float* __restrict__ rel_W1, const float* __restrict__ rel_b1) {
    extern __shared__ float sm[];
    float* s_w   = sm;                  // 8192 (geo_W2 then rel_W1)
    float* s_g1  = s_w + 8192;          // [64][128]
    float* s_e   = s_g1 + 8192;         // [128][129]
    float* s_geo = s_e + 128 * 129;     // [3][128]
    float* s_sum = s_geo + 384;         // [64]
    float* s_ss  = s_sum + 64;          // [64]
    int*   s_idx = (int*)(s_ss + 64);   // [128]
    int tid = threadIdx.x;
    int p0 = blockIdx.x * 8;
    int b = p0 >> 12; int n0 = p0 & (Nn - 1);

    if (tid < 128) s_idx[tid] = g_idx[p0 * Kk + tid];
    for (int i = tid; i < 8192; i += 256) s_w[i] = geo_W2[i];
    __syncthreads();
    if (tid < 128) {
        int nb = s_idx[tid] & (Nn - 1);   // within-batch for pts
        int pl = tid >> 4;
        const float* pb = pts + b * 3 * Nn;
#pragma unroll
        for (int c = 0; c < 3; c++)
            s_geo[c * 128 + tid] = pb[c * Nn + n0 + pl] - pb[c * Nn + nb];
    }
    __syncthreads();
    // g1 = relu(geo_W1 @ rel_geo + b1)
    for (int idx = tid; idx < 8192; idx += 256) {
        int h = idx >> 7, j = idx & 127;
        float v = fmaf(geo_W1[h * 3 + 2], s_geo[256 + j],
                  fmaf(geo_W1[h * 3 + 1], s_geo[128 + j],
                  fmaf(geo_W1[h * 3 + 0], s_geo[j], geo_b1[h])));
        s_g1[idx] = fmaxf(v, 0.f);
    }
    __syncthreads();
    int tx = tid & 15, ty = tid >> 4;
    // geo_emb = geo_W2 @ g1 + b2   (128x128, k=64)
    {
        float acc[8][8] = {};
        for (int kk = 0; kk < 64; kk++) {
            float a[8], bb[8];
#pragma unroll
            for (int i = 0; i < 8; i++) a[i] = s_w[(ty + 16 * i) * 64 + kk];
#pragma unroll
            for (int j = 0; j < 8; j++) bb[j] = s_g1[kk * 128 + tx + 16 * j];
#pragma unroll
            for (int i = 0; i < 8; i++)
#pragma unroll
                for (int j = 0; j < 8; j++) acc[i][j] = fmaf(a[i], bb[j], acc[i][j]);
        }
#pragma unroll
        for (int i = 0; i < 8; i++) {
            int c = ty + 16 * i;
            float bc = geo_b2[c];
#pragma unroll
            for (int j = 0; j < 8; j++) s_e[c * 129 + tx + 16 * j] = acc[i][j] + bc;
        }
    }
    __syncthreads();
    // rel = q - knn_k + geo_emb (in place)
    {
        int c = tid & 127, jh = tid >> 7;
        for (int jo = 0; jo < 64; jo++) {
            int j = jo * 2 + jh;
            int pl = j >> 4;
            int nb = s_idx[j];                // GLOBAL index into g_kT
            s_e[c * 129 + j] += g_qT[(p0 + pl) * Cc + c] - g_kT[nb * Cc + c];
        }
    }
    __syncthreads();
    for (int i = tid; i < 8192; i += 256) s_w[i] = rel_W1[i];
    __syncthreads();
    // t = rel_W1 @ rel + b1  (64x128, k=128), write + BN partials
    {
        float acc[4][8] = {};
        for (int cc = 0; cc < 128; cc++) {
            float a[4], bb[8];
#pragma unroll
            for (int i = 0; i < 4; i++) a[i] = s_w[(ty + 16 * i) * 128 + cc];
#pragma unroll
            for (int j = 0; j < 8; j++) bb[j] = s_e[cc * 129 + tx + 16 * j];
#pragma unroll
            for (int i = 0; i < 4; i++)
#pragma unroll
                for (int j = 0; j < 8; j++) acc[i][j] = fmaf(a[i], bb[j], acc[i][j]);
        }
#pragma unroll
        for (int i = 0; i < 4; i++) {
            int h = ty + 16 * i;
            float bh = rel_b1[h];
            float rs = 0.f, rss = 0.f;
#pragma unroll
            for (int j = 0; j < 8; j++) {
                float v = acc[i][j] + bh;     // column j*16+tx -> point p0+j, k=tx
                g_t[(long)(p0 + j) * (Hh * Kk) + h * Kk + tx] = v;
                rs += v; rss += v * v;
            }
#pragma unroll
            for (int off = 8; off; off >>= 1) {
                rs  += __shfl_xor_sync(0xffffffffu, rs, off);
                rss += __shfl_xor_sync(0xffffffffu, rss, off);
            }
            if (tx == 0) { s_sum[h] = rs; s_ss[h] = rss; }
        }
    }
    __syncthreads();
    if (tid < 64) {
        atomicAdd(&g_bnsum[tid], (double)s_sum[tid]);
        atomicAdd(&g_bnss[tid],  (double)s_ss[tid]);
    }
}

// ---------------- kernel 4: BN finalize ----------------
__global__ void k_bnfin(const float* __restrict__ rel_g, const float* __restrict__ rel_beta) {
    int h = threadIdx.x;
    if (h >= Hh) return;
    double cnt = (double)Pp * Kk;
    double m = g_bnsum[h] / cnt;
    double var = g_bnss[h] / cnt - m * m;
    double inv = 1.0 / sqrt(var + 1e-5);
    double sc = (double)rel_g[h] * inv;
    g_bnscale[h] = (float)sc;
    g_bnshift[h] = (float)((double)rel_beta[h] - m * sc);
}

// ---------------- kernel 5: pass2 (attn + aggregation), 8 points/block ----------------
__global__ __launch_bounds__(256) void k_pass2(const float* __restrict__ pts,
    const float* __restrict__ geo_W1, const float* __restrict__ geo_b1,
    const float* __restrict__ geo_W2, const float* __restrict__ geo_b2,
    const float* __restrict__ rel_W2, const float* __restrict__ rel_b2) {
    extern __shared__ float sm[];
    float* s_w   = sm;                  // 8192 (geo_W2 then rel_W2)
    float* s_g1  = s_w + 8192;          // [64][128] (g1 then h2)
    float* s_e   = s_g1 + 8192;         // [128][129] geo_emb
    float* s_l   = s_e + 128 * 129;     // [128][129] logits/attn
    float* s_geo = s_l + 128 * 129;     // [3][128]
    int*   s_idx = (int*)(s_geo + 384); // [128]
    int tid = threadIdx.x;
    int p0 = blockIdx.x * 8;
    int b = p0 >> 12; int n0 = p0 & (Nn - 1);

    if (tid < 128) s_idx[tid] = g_idx[p0 * Kk + tid];
    for (int i = tid; i < 8192; i += 256) s_w[i] = geo_W2[i];
    __syncthreads();
    if (tid < 128) {
        int nb = s_idx[tid] & (Nn - 1);
        int pl = tid >> 4;
        const float* pb = pts + b * 3 * Nn;
#pragma unroll
        for (int c = 0; c < 3; c++)
            s_geo[c * 128 + tid] = pb[c * Nn + n0 + pl] - pb[c * Nn + nb];
    }
    __syncthreads();
    // g1 = relu(geo_W1 @ rel_geo + b1)
    for (int idx = tid; idx < 8192; idx += 256) {
        int h = idx >> 7, j = idx & 127;
        float v = fmaf(geo_W1[h * 3 + 2], s_geo[256 + j],
                  fmaf(geo_W1[h * 3 + 1], s_geo[128 + j],
                  fmaf(geo_W1[h * 3 + 0], s_geo[j], geo_b1[h])));
        s_g1[h * 128 + j] = fmaxf(v, 0.f);
    }
    __syncthreads();
    int tx = tid & 15, ty = tid >> 4;
    // geo_emb = geo_W2 @ g1 + b2   (128x128, k=64)
    {
        float acc[8][8] = {};
        for (int kk = 0; kk < 64; kk++) {
            float a[8], bb[8];
#pragma unroll
            for (int i = 0; i < 8; i++) a[i] = s_w[(ty + 16 * i) * 64 + kk];
#pragma unroll
            for (int j = 0; j < 8; j++) bb[j] = s_g1[kk * 128 + tx + 16 * j];
#pragma unroll
            for (int i = 0; i < 8; i++)
#pragma unroll
                for (int j = 0; j < 8; j++) acc[i][j] = fmaf(a[i], bb[j], acc[i][j]);
        }
#pragma unroll
        for (int i = 0; i < 8; i++) {
            int c = ty + 16 * i;
            float bc = geo_b2[c];
#pragma unroll
            for (int j = 0; j < 8; j++) s_e[c * 129 + tx + 16 * j] = acc[i][j] + bc;
        }
    }
    __syncthreads();   // GEMM reads of s_g1 / s_w done
    // h2 = relu(BN(t)) into s_g1; also load rel_W2 into s_w
    for (int idx = tid; idx < 8192; idx += 256) {
        int h = idx >> 7, j = idx & 127;
        int pl = j >> 4, kki = j & 15;
        float tv = g_t[(long)(p0 + pl) * (Hh * Kk) + h * Kk + kki];
        s_g1[h * 128 + j] = fmaxf(fmaf(g_bnscale[h], tv, g_bnshift[h]), 0.f);
    }
    for (int i = tid; i < 8192; i += 256) s_w[i] = rel_W2[i];
    __syncthreads();
    // logits = rel_W2 @ h2 + b2   (128x128, k=64)
    {
        float acc[8][8] = {};
        for (int kk = 0; kk < 64; kk++) {
            float a[8], bb[8];
#pragma unroll
            for (int i = 0; i < 8; i++) a[i] = s_w[(ty + 16 * i) * 64 + kk];
#pragma unroll
            for (int j = 0; j < 8; j++) bb[j] = s_g1[kk * 128 + tx + 16 * j];
#pragma unroll
            for (int i = 0; i < 8; i++)
#pragma unroll
                for (int j = 0; j < 8; j++) acc[i][j] = fmaf(a[i], bb[j], acc[i][j]);
        }
#pragma unroll
        for (int i = 0; i < 8; i++) {
            int c = ty + 16 * i;
            float bc = rel_b2[c];
#pragma unroll
            for (int j = 0; j < 8; j++) s_l[c * 129 + tx + 16 * j] = acc[i][j] + bc;
        }
    }
    __syncthreads();
    // softmax over K per (c, point): 1024 rows of 16
    for (int r = tid; r < 1024; r += 256) {
        int c = r & 127, pl = r >> 7;
        float* row = s_l + c * 129 + pl * 16;
        float mx = row[0];
#pragma unroll
        for (int k = 1; k < 16; k++) mx = fmaxf(mx, row[k]);
        float ev[16]; float sum = 0.f;
#pragma unroll
        for (int k = 0; k < 16; k++) { ev[k] = __expf(row[k] - mx); sum += ev[k]; }
        float inv = 1.f / sum;
#pragma unroll
        for (int k = 0; k < 16; k++) row[k] = ev[k] * inv;
    }
    __syncthreads();
    // agg = sum_k attn * (v + geo_emb) + feats
    {
        int c = tid & 127, ph = tid >> 7;
        for (int pl = ph; pl < 8; pl += 2) {
            float acc = 0.f;
#pragma unroll
            for (int k = 0; k < 16; k++) {
                int j = pl * 16 + k;
                int nb = s_idx[j];            // GLOBAL index into g_vT
                acc = fmaf(s_l[c * 129 + j], g_vT[nb * Cc + c] + s_e[c * 129 + j], acc);
            }
            g_agg[(p0 + pl) * Cc + c] = acc + g_fT[(p0 + pl) * Cc + c];
        }
    }
}

// ---------------- kernel 6: out MLP layer 1 (relu), 128x128 tile, 8x8 ----------------
__global__ __launch_bounds__(256) void k_mlp1(const float* __restrict__ W, const float* __restrict__ bias) {
    __shared__ float As[128 * 33], Ws[128 * 33];
    int tid = threadIdx.x;
    int p0 = blockIdx.x * 128, o0 = blockIdx.y * 128;
    int tx = tid & 15, ty = tid >> 4;
    float acc[8][8] = {};
    for (int k0 = 0; k0 < Cc; k0 += 32) {
        int r = tid >> 1, kb = (tid & 1) * 16;
        const float* a = g_agg + (p0 + r) * Cc + k0 + kb;
#pragma unroll
        for (int u = 0; u < 16; u++) As[r * 33 + kb + u] = a[u];
        const float* wsrc = W + (o0 + r) * Cc + k0 + kb;
#pragma unroll
        for (int u = 0; u < 16; u++) Ws[r * 33 + kb + u] = wsrc[u];
        __syncthreads();
#pragma unroll 8
        for (int kk = 0; kk < 32; kk++) {
            float av[8], bv[8];
#pragma unroll
            for (int i = 0; i < 8; i++) av[i] = As[(ty + 16 * i) * 33 + kk];   // points
#pragma unroll
            for (int j = 0; j < 8; j++) bv[j] = Ws[(tx + 16 * j) * 33 + kk];   // outs
#pragma unroll
            for (int i = 0; i < 8; i++)
#pragma unroll
                for (int j = 0; j < 8; j++) acc[i][j] = fmaf(av[i], bv[j], acc[i][j]);
        }
        __syncthreads();
    }
#pragma unroll
    for (int i = 0; i < 8; i++) {
        int p = p0 + ty + 16 * i;
#pragma unroll
        for (int j = 0; j < 8; j++) {
            int o = o0 + tx + 16 * j;
            g_hid[p * (2 * Cc) + o] = fmaxf(acc[i][j] + bias[o], 0.f);
        }
    }
}

// ---------------- kernel 7: out MLP layer 2 + residual, 128x128 tile, 8x8 ----------------
__global__ __launch_bounds__(256) void k_mlp2(const float* __restrict__ W, const float* __restrict__ bias,
                                              float* __restrict__ out) {
    __shared__ float As[128 * 33], Ws[128 * 33];
    int tid = threadIdx.x;
    int p0 = blockIdx.x * 128;
    int tx = tid & 15, ty = tid >> 4;
    float acc[8][8] = {};   // i over outs, j over points
    for (int k0 = 0; k0 < 2 * Cc; k0 += 32) {
        int r = tid >> 1, kb = (tid & 1) * 16;
        const float* a = g_hid + (p0 + r) * (2 * Cc) + k0 + kb;
#pragma unroll
        for (int u = 0; u < 16; u++) As[r * 33 + kb + u] = a[u];
        const float* wsrc = W + r * (2 * Cc) + k0 + kb;   // 128 outs total
#pragma unroll
        for (int u = 0; u < 16; u++) Ws[r * 33 + kb + u] = wsrc[u];
        __syncthreads();
#pragma unroll 8
        for (int kk = 0; kk < 32; kk++) {
            float av[8], bv[8];
#pragma unroll
            for (int i = 0; i < 8; i++) av[i] = Ws[(ty + 16 * i) * 33 + kk];   // outs
#pragma unroll
            for (int j = 0; j < 8; j++) bv[j] = As[(tx + 16 * j) * 33 + kk];   // points
#pragma unroll
            for (int i = 0; i < 8; i++)
#pragma unroll
                for (int j = 0; j < 8; j++) acc[i][j] = fmaf(av[i], bv[j], acc[i][j]);
        }
        __syncthreads();
    }
#pragma unroll
    for (int i = 0; i < 8; i++) {
        int o = ty + 16 * i;
        float bo = bias[o];
#pragma unroll
        for (int j = 0; j < 8; j++) {
            int p = p0 + tx + 16 * j;
            int b = p >> 12, n = p & (Nn - 1);
            out[(long)b * Cc * Nn + o * Nn + n] = acc[i][j] + bo + g_agg[p * Cc + o];
        }
    }
}

// ---------------- launch ----------------
#define SMEM_P1 (33536 * 4)
#define SMEM_P2 (49920 * 4)

extern "C" void kernel_launch(void* const* d_in, const int* in_sizes, int n_in,
                              void* d_out, int out_size) {
    const float* pts   = (const float*)d_in[0];
    const float* feats = (const float*)d_in[1];
    const float* Wq = (const float*)d_in[2];  const float* bq = (const float*)d_in[3];
    const float* Wk = (const float*)d_in[4];  const float* bk = (const float*)d_in[5];
    const float* Wv = (const float*)d_in[6];  const float* bv = (const float*)d_in[7];
    const float* gW1 = (const float*)d_in[8]; const float* gb1 = (const float*)d_in[9];
    const float* gW2 = (const float*)d_in[10];const float* gb2 = (const float*)d_in[11];
    const float* rW1 = (const float*)d_in[12];const float* rb1 = (const float*)d_in[13];
    const float* rg  = (const float*)d_in[14];const float* rbe = (const float*)d_in[15];
    const float* rW2 = (const float*)d_in[16];const float* rb2 = (const float*)d_in[17];
    const float* oW1 = (const float*)d_in[18];const float* ob1 = (const float*)d_in[19];
    const float* oW2 = (const float*)d_in[20];const float* ob2 = (const float*)d_in[21];
    float* out = (float*)d_out;

    cudaFuncSetAttribute(k_pass1, cudaFuncAttributeMaxDynamicSharedMemorySize, SMEM_P1);
    cudaFuncSetAttribute(k_pass2, cudaFuncAttributeMaxDynamicSharedMemorySize, SMEM_P2);

    k_sq  <<<Pp / 256, 256>>>(pts);
    k_qkv <<<dim3(Pp / 128, 1, 3), 256>>>(feats, Wq, bq, Wk, bk, Wv, bv);
    k_knn <<<Pp / 8, 256>>>(pts);
    k_pass1<<<Pp / 8, 256, SMEM_P1>>>(pts, gW1, gb1, gW2, gb2, rW1, rb1);
    k_bnfin<<<1, 64>>>(rg, rbe);
    k_pass2<<<Pp / 8, 256, SMEM_P2>>>(pts, gW1, gb1, gW2, gb2, rW2, rb2);
    k_mlp1<<<dim3(Pp / 128, 2), 256>>>(oW1, ob1);
    k_mlp2<<<Pp / 128, 256>>>(oW2, ob2, out);
}